// round 1
// baseline (speedup 1.0000x reference)
#include <cuda_runtime.h>
#include <math.h>

// ---------------------------------------------------------------------------
// Problem constants
// ---------------------------------------------------------------------------
// 24 clips = (3 support videos + 3 query videos) x 4 segments
// clip input: (3, 16, 112, 112)
// Encoder: C3D. Head: cosine cost + sinkhorn on 4x4, output (3,3).

#define BN_SCALE_F 0.9999950000374996f  // 1/sqrt(1+1e-5)

// ---------------------------------------------------------------------------
// Static device scratch (no allocations allowed)
// ---------------------------------------------------------------------------
__device__ float g_pad[93007872];    // max padded input: conv2 in 24*64*18*58*58
__device__ float g_act[308281344];   // max conv out: conv1 out 24*64*16*112*112
__device__ float g_feat[24 * 8192];
__device__ float g_fc6[24 * 4096];
__device__ float g_fc7[24 * 4096];
__device__ float g_norm[24];
__device__ float g_cost[144];
__device__ float g_w1[64 * 96];      // conv1 weights K-padded 81->96

// ---------------------------------------------------------------------------
// Rearrange raw inputs (N, seg, T, C, H, W) -> padded clips [24][3][18][114][114]
// ---------------------------------------------------------------------------
__global__ void rearrange_pad_kernel(const float* __restrict__ sup,
                                     const float* __restrict__ qry,
                                     float* __restrict__ out, long total)
{
    long idx = (long)blockIdx.x * blockDim.x + threadIdx.x;
    if (idx >= total) return;
    long t = idx;
    int wx = (int)(t % 114); t /= 114;
    int hy = (int)(t % 114); t /= 114;
    int dz = (int)(t % 18);  t /= 18;
    int c  = (int)(t % 3);
    int clip = (int)(t / 3);
    float val = 0.0f;
    if (dz >= 1 && dz <= 16 && hy >= 1 && hy <= 112 && wx >= 1 && wx <= 112) {
        int tt = dz - 1, h = hy - 1, w = wx - 1;
        const float* src = (clip < 12) ? sup : qry;
        int cc = (clip < 12) ? clip : clip - 12;
        // src dims: (3, 4, 16, 3, 112, 112); cc = v*4 + seg
        long addr = ((((long)cc * 16 + tt) * 3 + c) * 112 + h) * 112 + w;
        val = src[addr];
    }
    out[idx] = val;
}

// conv1 weight prep: [64][81] -> [64][96] zero-padded along K
__global__ void w1prep_kernel(const float* __restrict__ w, float* __restrict__ out)
{
    int idx = blockIdx.x * blockDim.x + threadIdx.x;
    if (idx >= 64 * 96) return;
    int m = idx / 96, k = idx - m * 96;
    out[idx] = (k < 81) ? w[m * 81 + k] : 0.0f;
}

// ---------------------------------------------------------------------------
// Implicit-GEMM conv3d (stride 1, pad 1 already materialized in input).
//   A: weights [Cout][Kpad] row-major.  inp: padded [B][Cin][D+2][H+2][W+2]
//   out: [B][Cout][D][H][W] = relu(scale * (conv + bias))
//   GEMM: M=Cout, N=B*D*H*W, K=Cin*27.
// Key trick: im2col address = nbase(n) + koff(k)   (separable, no bounds checks)
// ---------------------------------------------------------------------------
template <int BM>
__global__ __launch_bounds__(256, 2)
void conv_gemm(const float* __restrict__ A, const float* __restrict__ inp,
               float* __restrict__ out, const float* __restrict__ bias, float scale,
               int Cin, int D, int H, int W, int Ktrue, int Kpad, int Cout, int Ntotal)
{
    constexpr int BNt = 128, BK = 16;
    constexpr int MR = (BM == 128) ? 8 : 4;
    const int Hp = H + 2, Wp = W + 2;
    const int HWp = Hp * Wp;
    const int chanStride = (D + 2) * HWp;
    const int HW = H * W;
    const int DHW = D * HW;

    __shared__ float sA[2][BK][BM];
    __shared__ float sB[2][BK][BNt];

    const int tid = threadIdx.x;
    const int tx = tid & 15;
    const int ty = tid >> 4;
    const int ntile = blockIdx.x;
    const int mtile = blockIdx.y;

    // ---- B-tile load mapping: thread loads 8 consecutive n at one k-row ----
    const int krow = ty;
    const int n0 = tx * 8;
    int nbase[8];
#pragma unroll
    for (int j = 0; j < 8; ++j) {
        int n = ntile * BNt + n0 + j;
        if (n >= Ntotal) n = Ntotal - 1;
        int b = n / DHW;
        int rem = n - b * DHW;
        int d = rem / HW;
        int r2 = rem - d * HW;
        int h = r2 / W;
        int w = r2 - h * W;
        nbase[j] = b * Cin * chanStride + d * HWp + h * Wp + w;
    }

    // ---- A-tile load mapping ----
    const int am = tid & (BM - 1);
    const int akg = tid / BM;  // BM=128 -> 0..1 (8 k each); BM=64 -> 0..3 (4 k each)
    const float* Aptr = A + (size_t)(mtile * BM + am) * Kpad;

    float4 stA0, stA1;
    float stB[8];
    int koff = 0;

    auto LOADK = [&](int k0_) {
        if constexpr (BM == 128) {
            stA0 = *(const float4*)(Aptr + k0_ + akg * 8);
            stA1 = *(const float4*)(Aptr + k0_ + akg * 8 + 4);
        } else {
            stA0 = *(const float4*)(Aptr + k0_ + akg * 4);
        }
        int kg_ = k0_ + krow;
        int ke_ = (kg_ < Ktrue) ? kg_ : 0;  // padded-K -> weight is 0, any valid addr
        int ci_ = ke_ / 27;
        int r_ = ke_ - ci_ * 27;
        int kd_ = r_ / 9; r_ -= kd_ * 9;
        int kh_ = r_ / 3;
        int kw_ = r_ - kh_ * 3;
        koff = ci_ * chanStride + kd_ * HWp + kh_ * Wp + kw_;
#pragma unroll
        for (int j = 0; j < 8; ++j) stB[j] = __ldg(inp + nbase[j] + koff);
    };

    auto STORETILE = [&](int bf_) {
        if constexpr (BM == 128) {
            int kb_ = akg * 8;
            sA[bf_][kb_ + 0][am] = stA0.x;
            sA[bf_][kb_ + 1][am] = stA0.y;
            sA[bf_][kb_ + 2][am] = stA0.z;
            sA[bf_][kb_ + 3][am] = stA0.w;
            sA[bf_][kb_ + 4][am] = stA1.x;
            sA[bf_][kb_ + 5][am] = stA1.y;
            sA[bf_][kb_ + 6][am] = stA1.z;
            sA[bf_][kb_ + 7][am] = stA1.w;
        } else {
            int kb_ = akg * 4;
            sA[bf_][kb_ + 0][am] = stA0.x;
            sA[bf_][kb_ + 1][am] = stA0.y;
            sA[bf_][kb_ + 2][am] = stA0.z;
            sA[bf_][kb_ + 3][am] = stA0.w;
        }
        *(float4*)&sB[bf_][krow][n0]     = make_float4(stB[0], stB[1], stB[2], stB[3]);
        *(float4*)&sB[bf_][krow][n0 + 4] = make_float4(stB[4], stB[5], stB[6], stB[7]);
    };

    float acc[MR][8];
#pragma unroll
    for (int i = 0; i < MR; ++i)
#pragma unroll
        for (int j = 0; j < 8; ++j) acc[i][j] = 0.0f;

    const int KT = Kpad / BK;

    LOADK(0);
    STORETILE(0);
    __syncthreads();

    for (int kt = 0; kt < KT; ++kt) {
        int buf = kt & 1;
        if (kt + 1 < KT) LOADK((kt + 1) * BK);
#pragma unroll
        for (int kk = 0; kk < BK; ++kk) {
            float bf[8], af[MR];
            float4 b0 = *(const float4*)&sB[buf][kk][tx * 4];
            float4 b1 = *(const float4*)&sB[buf][kk][64 + tx * 4];
            bf[0] = b0.x; bf[1] = b0.y; bf[2] = b0.z; bf[3] = b0.w;
            bf[4] = b1.x; bf[5] = b1.y; bf[6] = b1.z; bf[7] = b1.w;
            float4 a0 = *(const float4*)&sA[buf][kk][ty * 4];
            af[0] = a0.x; af[1] = a0.y; af[2] = a0.z; af[3] = a0.w;
            if constexpr (BM == 128) {
                float4 a1 = *(const float4*)&sA[buf][kk][64 + ty * 4];
                af[4] = a1.x; af[5] = a1.y; af[6] = a1.z; af[7] = a1.w;
            }
#pragma unroll
            for (int i = 0; i < MR; ++i)
#pragma unroll
                for (int j = 0; j < 8; ++j) acc[i][j] += af[i] * bf[j];
        }
        if (kt + 1 < KT) STORETILE(buf ^ 1);
        __syncthreads();
    }

    // ---- epilogue: bias + scale + relu, scatter to NCDHW ----
#pragma unroll
    for (int j = 0; j < 8; ++j) {
        int col = (j < 4) ? (tx * 4 + j) : (64 + tx * 4 + j - 4);
        int n = ntile * BNt + col;
        if (n >= Ntotal) continue;
        int b = n / DHW;
        int rem = n - b * DHW;
        size_t obase = ((size_t)b * Cout) * DHW + rem;
#pragma unroll
        for (int i = 0; i < MR; ++i) {
            int row = (i < 4) ? (ty * 4 + i) : (64 + ty * 4 + i - 4);
            int m = mtile * BM + row;
            float v = scale * (acc[i][j] + bias[m]);
            out[obase + (size_t)m * DHW] = fmaxf(v, 0.0f);
        }
    }
}

// ---------------------------------------------------------------------------
// Fused maxpool + conv-halo-pad. Writes [B][C][Do+2cp][Ho+2cp][Wo+2cp].
// Identity pool (k=s=1) gives pure padding. cp=0 writes plain pooled output.
// ---------------------------------------------------------------------------
__global__ void pool_pad_kernel(const float* __restrict__ in, float* __restrict__ out,
                                int Bc, int C, int D, int H, int W,
                                int kd, int kh, int kw, int sd, int sh, int sw,
                                int pd, int ph, int pw,
                                int Do, int Ho, int Wo, int cp, long total)
{
    long idx = (long)blockIdx.x * blockDim.x + threadIdx.x;
    if (idx >= total) return;
    int Hp = Ho + 2 * cp, Wp = Wo + 2 * cp, Dp = Do + 2 * cp;
    long t = idx;
    int x = (int)(t % Wp); t /= Wp;
    int y = (int)(t % Hp); t /= Hp;
    int z = (int)(t % Dp); t /= Dp;
    int c = (int)(t % C);
    int b = (int)(t / C);
    float v = 0.0f;
    int od = z - cp, oh = y - cp, ow = x - cp;
    if (od >= 0 && od < Do && oh >= 0 && oh < Ho && ow >= 0 && ow < Wo) {
        float m = -3.4e38f;
        int id0 = od * sd - pd, ih0 = oh * sh - ph, iw0 = ow * sw - pw;
        const float* base = in + ((long)(b * C + c)) * D * H * W;
        for (int a = 0; a < kd; ++a) {
            int id = id0 + a;
            if (id < 0 || id >= D) continue;
            for (int e = 0; e < kh; ++e) {
                int ih = ih0 + e;
                if (ih < 0 || ih >= H) continue;
                for (int f = 0; f < kw; ++f) {
                    int iw = iw0 + f;
                    if (iw < 0 || iw >= W) continue;
                    float q = base[((long)id * H + ih) * W + iw];
                    m = fmaxf(m, q);
                }
            }
        }
        v = m;
    }
    out[idx] = v;
}

// ---------------------------------------------------------------------------
// FC: y[n][m] = relu(scale * (x[n]. W[m] + b[m]))
// ---------------------------------------------------------------------------
__global__ void fc_relu_kernel(const float* __restrict__ x, const float* __restrict__ W,
                               const float* __restrict__ b, float* __restrict__ y,
                               int K, int M, int N, float scale)
{
    int idx = blockIdx.x * blockDim.x + threadIdx.x;
    if (idx >= M * N) return;
    int m = idx / N;
    int n = idx - m * N;
    const float4* wr = (const float4*)(W + (size_t)m * K);
    const float4* xr = (const float4*)(x + (size_t)n * K);
    float s = 0.0f;
    int K4 = K >> 2;
#pragma unroll 4
    for (int k = 0; k < K4; ++k) {
        float4 a = wr[k];
        float4 c = xr[k];
        s += a.x * c.x + a.y * c.y + a.z * c.z + a.w * c.w;
    }
    float v = scale * (s + b[m]);
    y[(size_t)n * M + m] = fmaxf(v, 0.0f);
}

__global__ void rownorm_kernel(const float* __restrict__ x, float* __restrict__ nrm, int K)
{
    int row = blockIdx.x;
    float s = 0.0f;
    for (int k = threadIdx.x; k < K; k += 128) {
        float v = x[(size_t)row * K + k];
        s += v * v;
    }
    __shared__ float sm[128];
    sm[threadIdx.x] = s;
    __syncthreads();
    for (int o = 64; o > 0; o >>= 1) {
        if (threadIdx.x < o) sm[threadIdx.x] += sm[threadIdx.x + o];
        __syncthreads();
    }
    if (threadIdx.x == 0) nrm[row] = sqrtf(sm[0]);
}

// sem_cost[q][s][i][j] = 1 - cos(query[12+q*4+i], support[s*4+j])
__global__ void cost_kernel(const float* __restrict__ feat, const float* __restrict__ nrm,
                            float* __restrict__ cost)
{
    int bi = blockIdx.x;  // ((q*3+s)*4+i)*4+j
    int j = bi & 3, t2 = bi >> 2;
    int i = t2 & 3, t3 = t2 >> 2;
    int s = t3 % 3, q = t3 / 3;
    int qrow = 12 + q * 4 + i;
    int srow = s * 4 + j;
    const float* a = feat + (size_t)qrow * 4096;
    const float* c = feat + (size_t)srow * 4096;
    float p = 0.0f;
    for (int k = threadIdx.x; k < 4096; k += 128) p += a[k] * c[k];
    __shared__ float sm[128];
    sm[threadIdx.x] = p;
    __syncthreads();
    for (int o = 64; o > 0; o >>= 1) {
        if (threadIdx.x < o) sm[threadIdx.x] += sm[threadIdx.x + o];
        __syncthreads();
    }
    if (threadIdx.x == 0)
        cost[bi] = 1.0f - sm[0] / ((nrm[qrow] + 1e-8f) * (nrm[srow] + 1e-8f));
}

// 9 independent 4x4 sinkhorn problems, 100 iterations each. out = -trans_cost.
__global__ void sinkhorn_kernel(const float* __restrict__ cost, float* __restrict__ outp)
{
    int t = threadIdx.x;
    if (t >= 9) return;
    float sem[16], Km[16];
    for (int i = 0; i < 4; ++i)
        for (int j = 0; j < 4; ++j) {
            float sc = cost[t * 16 + i * 4 + j];
            float ti = i * 0.25f, tj = j * 0.25f;
            float d2 = (ti - tj) * (ti - tj);
            float pos = expf(-1.0f / (d2 + 1.0f));  // PHI = 1
            sem[i * 4 + j] = sc;
            Km[i * 4 + j] = expf(-7.0f * (sc + 0.4f * pos));
        }
    float u[4] = {0.25f, 0.25f, 0.25f, 0.25f}, v[4];
    for (int it = 0; it < 100; ++it) {
        for (int j = 0; j < 4; ++j) {
            float s = 1e-9f;
            for (int i = 0; i < 4; ++i) s += Km[i * 4 + j] * u[i];
            v[j] = 0.25f / s;
        }
        for (int i = 0; i < 4; ++i) {
            float s = 1e-9f;
            for (int j = 0; j < 4; ++j) s += Km[i * 4 + j] * v[j];
            u[i] = 0.25f / s;
        }
    }
    for (int j = 0; j < 4; ++j) {
        float s = 1e-9f;
        for (int i = 0; i < 4; ++i) s += Km[i * 4 + j] * u[i];
        v[j] = 0.25f / s;
    }
    float tr = 0.0f;
    for (int i = 0; i < 4; ++i)
        for (int j = 0; j < 4; ++j)
            tr += u[i] * Km[i * 4 + j] * v[j] * sem[i * 4 + j];
    outp[t] = -tr;  // (q, way) row-major, N_SHOT=1
}

// ---------------------------------------------------------------------------
// Driver
// ---------------------------------------------------------------------------
static inline int cdiv_l(long a, long b) { return (int)((a + b - 1) / b); }

extern "C" void kernel_launch(void* const* d_in, const int* in_sizes, int n_in,
                              void* d_out, int out_size)
{
    const float* sup  = (const float*)d_in[0];
    const float* qry  = (const float*)d_in[1];
    const float* w1   = (const float*)d_in[2];
    const float* b1   = (const float*)d_in[3];
    const float* w2   = (const float*)d_in[4];
    const float* b2   = (const float*)d_in[5];
    const float* w3a  = (const float*)d_in[6];
    const float* b3a  = (const float*)d_in[7];
    const float* w3b  = (const float*)d_in[8];
    const float* b3b  = (const float*)d_in[9];
    const float* w4a  = (const float*)d_in[10];
    const float* b4a  = (const float*)d_in[11];
    const float* w4b  = (const float*)d_in[12];
    const float* b4b  = (const float*)d_in[13];
    const float* w5a  = (const float*)d_in[14];
    const float* b5a  = (const float*)d_in[15];
    const float* w5b  = (const float*)d_in[16];
    const float* b5b  = (const float*)d_in[17];
    const float* fw6  = (const float*)d_in[18];
    const float* fb6  = (const float*)d_in[19];
    const float* fw7  = (const float*)d_in[20];
    const float* fb7  = (const float*)d_in[21];

    float *pad, *act, *feat, *fc6o, *fc7o, *nrm, *cst, *w1p;
    cudaGetSymbolAddress((void**)&pad,  g_pad);
    cudaGetSymbolAddress((void**)&act,  g_act);
    cudaGetSymbolAddress((void**)&feat, g_feat);
    cudaGetSymbolAddress((void**)&fc6o, g_fc6);
    cudaGetSymbolAddress((void**)&fc7o, g_fc7);
    cudaGetSymbolAddress((void**)&nrm,  g_norm);
    cudaGetSymbolAddress((void**)&cst,  g_cost);
    cudaGetSymbolAddress((void**)&w1p,  g_w1);

    const float SC = BN_SCALE_F;

    // input rearrange + pad -> [24][3][18][114][114]
    {
        long total = 24L * 3 * 18 * 114 * 114;
        rearrange_pad_kernel<<<cdiv_l(total, 256), 256>>>(sup, qry, pad, total);
    }
    w1prep_kernel<<<cdiv_l(64 * 96, 256), 256>>>(w1, w1p);

    // conv1: 3->64, (16,112,112), K 81->96
    conv_gemm<64><<<dim3(37632, 1), 256>>>(w1p, pad, act, b1, SC,
                                           3, 16, 112, 112, 81, 96, 64, 4816896);
    // pool1 (1,2,2) + pad -> [24][64][18][58][58]
    pool_pad_kernel<<<cdiv_l(93007872L, 256), 256>>>(act, pad, 24, 64, 16, 112, 112,
                                                     1, 2, 2, 1, 2, 2, 0, 0, 0,
                                                     16, 56, 56, 1, 93007872L);
    // conv2: 64->128, (16,56,56)
    conv_gemm<128><<<dim3(9408, 1), 256>>>(w2, pad, act, b2, SC,
                                           64, 16, 56, 56, 1728, 1728, 128, 1204224);
    // pool2 (2,2,2) + pad -> [24][128][10][30][30]
    pool_pad_kernel<<<cdiv_l(27648000L, 256), 256>>>(act, pad, 24, 128, 16, 56, 56,
                                                     2, 2, 2, 2, 2, 2, 0, 0, 0,
                                                     8, 28, 28, 1, 27648000L);
    // conv3a: 128->256, (8,28,28), no BN scale
    conv_gemm<128><<<dim3(1176, 2), 256>>>(w3a, pad, act, b3a, 1.0f,
                                           128, 8, 28, 28, 3456, 3456, 256, 150528);
    // identity pad
    pool_pad_kernel<<<cdiv_l(55296000L, 256), 256>>>(act, pad, 24, 256, 8, 28, 28,
                                                     1, 1, 1, 1, 1, 1, 0, 0, 0,
                                                     8, 28, 28, 1, 55296000L);
    // conv3b: 256->256
    conv_gemm<128><<<dim3(1176, 2), 256>>>(w3b, pad, act, b3b, SC,
                                           256, 8, 28, 28, 6912, 6912, 256, 150528);
    // pool3 -> [24][256][6][16][16]
    pool_pad_kernel<<<cdiv_l(9437184L, 256), 256>>>(act, pad, 24, 256, 8, 28, 28,
                                                    2, 2, 2, 2, 2, 2, 0, 0, 0,
                                                    4, 14, 14, 1, 9437184L);
    // conv4a: 256->512, (4,14,14), no BN scale
    conv_gemm<128><<<dim3(147, 4), 256>>>(w4a, pad, act, b4a, 1.0f,
                                          256, 4, 14, 14, 6912, 6912, 512, 18816);
    // identity pad
    pool_pad_kernel<<<cdiv_l(18874368L, 256), 256>>>(act, pad, 24, 512, 4, 14, 14,
                                                     1, 1, 1, 1, 1, 1, 0, 0, 0,
                                                     4, 14, 14, 1, 18874368L);
    // conv4b: 512->512
    conv_gemm<128><<<dim3(147, 4), 256>>>(w4b, pad, act, b4b, SC,
                                          512, 4, 14, 14, 13824, 13824, 512, 18816);
    // pool4 -> [24][512][4][9][9]
    pool_pad_kernel<<<cdiv_l(3981312L, 256), 256>>>(act, pad, 24, 512, 4, 14, 14,
                                                    2, 2, 2, 2, 2, 2, 0, 0, 0,
                                                    2, 7, 7, 1, 3981312L);
    // conv5a: 512->512, (2,7,7), no BN scale
    conv_gemm<128><<<dim3(19, 4), 256>>>(w5a, pad, act, b5a, 1.0f,
                                         512, 2, 7, 7, 13824, 13824, 512, 2352);
    // identity pad
    pool_pad_kernel<<<cdiv_l(3981312L, 256), 256>>>(act, pad, 24, 512, 2, 7, 7,
                                                    1, 1, 1, 1, 1, 1, 0, 0, 0,
                                                    2, 7, 7, 1, 3981312L);
    // conv5b: 512->512
    conv_gemm<128><<<dim3(19, 4), 256>>>(w5b, pad, act, b5b, SC,
                                         512, 2, 7, 7, 13824, 13824, 512, 2352);
    // pool5 (2,2,2) pad(0,1,1) -> features [24][8192]
    pool_pad_kernel<<<cdiv_l(196608L, 256), 256>>>(act, feat, 24, 512, 2, 7, 7,
                                                   2, 2, 2, 2, 2, 2, 0, 1, 1,
                                                   1, 4, 4, 0, 196608L);
    // fc6, fc7
    fc_relu_kernel<<<cdiv_l(4096 * 24, 256), 256>>>(feat, fw6, fb6, fc6o, 8192, 4096, 24, SC);
    fc_relu_kernel<<<cdiv_l(4096 * 24, 256), 256>>>(fc6o, fw7, fb7, fc7o, 4096, 4096, 24, SC);

    // head
    rownorm_kernel<<<24, 128>>>(fc7o, nrm, 4096);
    cost_kernel<<<144, 128>>>(fc7o, nrm, cst);
    sinkhorn_kernel<<<1, 32>>>(cst, (float*)d_out);
}

// round 4
// speedup vs baseline: 1.0792x; 1.0792x over previous
#include <cuda_runtime.h>
#include <math.h>

#define BN_SCALE_F 0.9999950000374996f  // 1/sqrt(1+1e-5)

// ---------------------------------------------------------------------------
// Static device scratch
// ---------------------------------------------------------------------------
__device__ float g_pad[93007872];    // max padded input: conv2 in 24*64*18*58*58
__device__ float g_act[308281344];   // max conv out: conv1 out 24*64*16*112*112
__device__ float g_feat[24 * 8192];
__device__ float g_fc6[24 * 4096];
__device__ float g_fc7[24 * 4096];
__device__ float g_norm[24];
__device__ float g_cost[144];
__device__ float g_w1[64 * 96];      // conv1 weights K-padded 81->96

// ---------------------------------------------------------------------------
// Packed fp32x2 helpers (Blackwell native; 2x fp32 FMA throughput)
// ---------------------------------------------------------------------------
__device__ __forceinline__ void ffma2(unsigned long long& d,
                                      unsigned long long a,
                                      unsigned long long b)
{
    asm("fma.rn.f32x2 %0, %1, %2, %0;" : "+l"(d) : "l"(a), "l"(b));
}
__device__ __forceinline__ unsigned long long splat2(float x)
{
    unsigned long long r;
    asm("mov.b64 %0, {%1, %1};" : "=l"(r) : "f"(x));
    return r;
}
__device__ __forceinline__ void unpack2(unsigned long long p, float& lo, float& hi)
{
    asm("mov.b64 {%0, %1}, %2;" : "=f"(lo), "=f"(hi) : "l"(p));
}

// ---------------------------------------------------------------------------
// Rearrange raw inputs -> padded clips [24][3][18][114][114]
// grid.y = clip*3 + c  (72 planes); grid.x covers 18*114*114
// ---------------------------------------------------------------------------
__global__ void rearrange_pad_kernel(const float* __restrict__ sup,
                                     const float* __restrict__ qry,
                                     float* __restrict__ out)
{
    const int plane = blockIdx.y;          // clip*3 + c
    const int clip = plane / 3;
    const int c = plane - clip * 3;
    const int s = blockIdx.x * blockDim.x + threadIdx.x;
    const int HWp = 114 * 114;
    if (s >= 18 * HWp) return;
    int dz = s / HWp;
    int r = s - dz * HWp;
    int hy = r / 114;
    int wx = r - hy * 114;
    float val = 0.0f;
    if (dz >= 1 && dz <= 16 && hy >= 1 && hy <= 112 && wx >= 1 && wx <= 112) {
        int tt = dz - 1, h = hy - 1, w = wx - 1;
        const float* src = (clip < 12) ? sup : qry;
        int cc = (clip < 12) ? clip : clip - 12;
        long addr = ((((long)cc * 16 + tt) * 3 + c) * 112 + h) * 112 + w;
        val = src[addr];
    }
    out[(long)plane * 18 * HWp + s] = val;
}

// conv1 weight prep: [64][81] -> [64][96] zero-padded along K
__global__ void w1prep_kernel(const float* __restrict__ w, float* __restrict__ out)
{
    int idx = blockIdx.x * blockDim.x + threadIdx.x;
    if (idx >= 64 * 96) return;
    int m = idx / 96, k = idx - m * 96;
    out[idx] = (k < 81) ? w[m * 81 + k] : 0.0f;
}

// ---------------------------------------------------------------------------
// Implicit-GEMM conv3d using packed f32x2 FMAs.
//   A: weights [Cout][Kpad].  inp: padded [B][Cin][D+2][H+2][W+2]
//   out: [B][Cout][D][H][W] = relu(scale * (conv + bias))
// ---------------------------------------------------------------------------
template <int BM>
__global__ __launch_bounds__(256, 2)
void conv_gemm(const float* __restrict__ A, const float* __restrict__ inp,
               float* __restrict__ out, const float* __restrict__ bias, float scale,
               int Cin, int D, int H, int W, int Ktrue, int Kpad, int Cout, int Ntotal)
{
    constexpr int BNt = 128, BK = 16;
    constexpr int MR = (BM == 128) ? 8 : 4;
    const int Hp = H + 2, Wp = W + 2;
    const int HWp = Hp * Wp;
    const int chanStride = (D + 2) * HWp;
    const int HW = H * W;
    const int DHW = D * HW;

    __shared__ float sA[2][BK][BM];
    __shared__ float sB[2][BK][BNt];

    const int tid = threadIdx.x;
    const int tx = tid & 15;
    const int ty = tid >> 4;
    const int ntile = blockIdx.x;
    const int mtile = blockIdx.y;

    // ---- B-tile load mapping ----
    const int krow = ty;
    const int n0 = tx * 8;
    int nbase[8];
#pragma unroll
    for (int j = 0; j < 8; ++j) {
        int n = ntile * BNt + n0 + j;
        if (n >= Ntotal) n = Ntotal - 1;
        int b = n / DHW;
        int rem = n - b * DHW;
        int d = rem / HW;
        int r2 = rem - d * HW;
        int h = r2 / W;
        int w = r2 - h * W;
        nbase[j] = b * Cin * chanStride + d * HWp + h * Wp + w;
    }

    // ---- A-tile load mapping ----
    const int am = tid & (BM - 1);
    const int akg = tid / BM;
    const float* Aptr = A + (size_t)(mtile * BM + am) * Kpad;

    float4 stA0, stA1;
    float stB[8];
    int koff = 0;

    auto LOADK = [&](int k0_) {
        if constexpr (BM == 128) {
            stA0 = *(const float4*)(Aptr + k0_ + akg * 8);
            stA1 = *(const float4*)(Aptr + k0_ + akg * 8 + 4);
        } else {
            stA0 = *(const float4*)(Aptr + k0_ + akg * 4);
        }
        int kg_ = k0_ + krow;
        int ke_ = (kg_ < Ktrue) ? kg_ : 0;
        int ci_ = ke_ / 27;
        int r_ = ke_ - ci_ * 27;
        int kd_ = r_ / 9; r_ -= kd_ * 9;
        int kh_ = r_ / 3;
        int kw_ = r_ - kh_ * 3;
        koff = ci_ * chanStride + kd_ * HWp + kh_ * Wp + kw_;
#pragma unroll
        for (int j = 0; j < 8; ++j) stB[j] = __ldg(inp + nbase[j] + koff);
    };

    auto STORETILE = [&](int bf_) {
        if constexpr (BM == 128) {
            int kb_ = akg * 8;
            sA[bf_][kb_ + 0][am] = stA0.x;
            sA[bf_][kb_ + 1][am] = stA0.y;
            sA[bf_][kb_ + 2][am] = stA0.z;
            sA[bf_][kb_ + 3][am] = stA0.w;
            sA[bf_][kb_ + 4][am] = stA1.x;
            sA[bf_][kb_ + 5][am] = stA1.y;
            sA[bf_][kb_ + 6][am] = stA1.z;
            sA[bf_][kb_ + 7][am] = stA1.w;
        } else {
            int kb_ = akg * 4;
            sA[bf_][kb_ + 0][am] = stA0.x;
            sA[bf_][kb_ + 1][am] = stA0.y;
            sA[bf_][kb_ + 2][am] = stA0.z;
            sA[bf_][kb_ + 3][am] = stA0.w;
        }
        *(float4*)&sB[bf_][krow][n0]     = make_float4(stB[0], stB[1], stB[2], stB[3]);
        *(float4*)&sB[bf_][krow][n0 + 4] = make_float4(stB[4], stB[5], stB[6], stB[7]);
    };

    // Packed accumulators: acc2[i][jp] = (col 2jp, col 2jp+1) pair
    unsigned long long acc2[MR][4];
#pragma unroll
    for (int i = 0; i < MR; ++i)
#pragma unroll
        for (int jp = 0; jp < 4; ++jp) acc2[i][jp] = 0ULL;

    const int KT = Kpad / BK;

    LOADK(0);
    STORETILE(0);
    __syncthreads();

    for (int kt = 0; kt < KT; ++kt) {
        int buf = kt & 1;
        if (kt + 1 < KT) LOADK((kt + 1) * BK);
#pragma unroll
        for (int kk = 0; kk < BK; ++kk) {
            // B pairs: 16B loads reinterpreted as 2x packed f32x2
            ulonglong2 b0 = *(const ulonglong2*)&sB[buf][kk][tx * 4];
            ulonglong2 b1 = *(const ulonglong2*)&sB[buf][kk][64 + tx * 4];
            unsigned long long bp[4] = {b0.x, b0.y, b1.x, b1.y};
            float af[MR];
            float4 a0 = *(const float4*)&sA[buf][kk][ty * 4];
            af[0] = a0.x; af[1] = a0.y; af[2] = a0.z; af[3] = a0.w;
            if constexpr (BM == 128) {
                float4 a1 = *(const float4*)&sA[buf][kk][64 + ty * 4];
                af[4] = a1.x; af[5] = a1.y; af[6] = a1.z; af[7] = a1.w;
            }
#pragma unroll
            for (int i = 0; i < MR; ++i) {
                unsigned long long a2 = splat2(af[i]);
                ffma2(acc2[i][0], a2, bp[0]);
                ffma2(acc2[i][1], a2, bp[1]);
                ffma2(acc2[i][2], a2, bp[2]);
                ffma2(acc2[i][3], a2, bp[3]);
            }
        }
        if (kt + 1 < KT) STORETILE(buf ^ 1);
        __syncthreads();
    }

    // ---- epilogue: bias + scale + relu, scatter to NCDHW ----
#pragma unroll
    for (int jp = 0; jp < 4; ++jp) {
        // jp 0,1 -> cols tx*4 + {0,1},{2,3}; jp 2,3 -> cols 64+tx*4 + {0,1},{2,3}
        int colbase = (jp < 2) ? (tx * 4 + jp * 2) : (64 + tx * 4 + (jp - 2) * 2);
#pragma unroll
        for (int half = 0; half < 2; ++half) {
            int n = ntile * BNt + colbase + half;
            if (n >= Ntotal) continue;
            int b = n / DHW;
            int rem = n - b * DHW;
            size_t obase = ((size_t)b * Cout) * DHW + rem;
#pragma unroll
            for (int i = 0; i < MR; ++i) {
                int row = (i < 4) ? (ty * 4 + i) : (64 + ty * 4 + i - 4);
                int m = mtile * BM + row;
                float lo, hi;
                unpack2(acc2[i][jp], lo, hi);
                float v = scale * (((half == 0) ? lo : hi) + bias[m]);
                out[obase + (size_t)m * DHW] = fmaxf(v, 0.0f);
            }
        }
    }
}

// ---------------------------------------------------------------------------
// Fused maxpool + conv-halo-pad. grid.y = b*C + c (plane); 32-bit indexing.
// Writes [plane][Do+2cp][Ho+2cp][Wo+2cp]. Identity pool (k=s=1) = pure pad.
// ---------------------------------------------------------------------------
__global__ void pool_pad_kernel(const float* __restrict__ in, float* __restrict__ out,
                                int D, int H, int W,
                                int kd, int kh, int kw, int sd, int sh, int sw,
                                int pd, int ph, int pw,
                                int Do, int Ho, int Wo, int cp)
{
    const int plane = blockIdx.y;
    const int Hp = Ho + 2 * cp, Wp = Wo + 2 * cp, Dp = Do + 2 * cp;
    const int HWp = Hp * Wp;
    const int s = blockIdx.x * blockDim.x + threadIdx.x;
    if (s >= Dp * HWp) return;
    int z = s / HWp;
    int r = s - z * HWp;
    int y = r / Wp;
    int x = r - y * Wp;
    float v = 0.0f;
    int od = z - cp, oh = y - cp, ow = x - cp;
    if (od >= 0 && od < Do && oh >= 0 && oh < Ho && ow >= 0 && ow < Wo) {
        float m = -3.4e38f;
        int id0 = od * sd - pd, ih0 = oh * sh - ph, iw0 = ow * sw - pw;
        const float* base = in + (long)plane * D * H * W;
        for (int a = 0; a < kd; ++a) {
            int id = id0 + a;
            if (id < 0 || id >= D) continue;
            for (int e = 0; e < kh; ++e) {
                int ih = ih0 + e;
                if (ih < 0 || ih >= H) continue;
                for (int f = 0; f < kw; ++f) {
                    int iw = iw0 + f;
                    if (iw < 0 || iw >= W) continue;
                    float q = base[(id * H + ih) * W + iw];
                    m = fmaxf(m, q);
                }
            }
        }
        v = m;
    }
    out[(long)plane * Dp * HWp + s] = v;
}

// ---------------------------------------------------------------------------
// FC: y[n][m] = relu(scale * (x[n] . W[m] + b[m]))
// ---------------------------------------------------------------------------
__global__ void fc_relu_kernel(const float* __restrict__ x, const float* __restrict__ W,
                               const float* __restrict__ b, float* __restrict__ y,
                               int K, int M, int N, float scale)
{
    int idx = blockIdx.x * blockDim.x + threadIdx.x;
    if (idx >= M * N) return;
    int m = idx / N;
    int n = idx - m * N;
    const float4* wr = (const float4*)(W + (size_t)m * K);
    const float4* xr = (const float4*)(x + (size_t)n * K);
    float s = 0.0f;
    int K4 = K >> 2;
#pragma unroll 4
    for (int k = 0; k < K4; ++k) {
        float4 a = wr[k];
        float4 c = xr[k];
        s += a.x * c.x + a.y * c.y + a.z * c.z + a.w * c.w;
    }
    float v = scale * (s + b[m]);
    y[(size_t)n * M + m] = fmaxf(v, 0.0f);
}

__global__ void rownorm_kernel(const float* __restrict__ x, float* __restrict__ nrm, int K)
{
    int row = blockIdx.x;
    float s = 0.0f;
    for (int k = threadIdx.x; k < K; k += 128) {
        float v = x[(size_t)row * K + k];
        s += v * v;
    }
    __shared__ float sm[128];
    sm[threadIdx.x] = s;
    __syncthreads();
    for (int o = 64; o > 0; o >>= 1) {
        if (threadIdx.x < o) sm[threadIdx.x] += sm[threadIdx.x + o];
        __syncthreads();
    }
    if (threadIdx.x == 0) nrm[row] = sqrtf(sm[0]);
}

__global__ void cost_kernel(const float* __restrict__ feat, const float* __restrict__ nrm,
                            float* __restrict__ cost)
{
    int bi = blockIdx.x;  // ((q*3+s)*4+i)*4+j
    int j = bi & 3, t2 = bi >> 2;
    int i = t2 & 3, t3 = t2 >> 2;
    int s = t3 % 3, q = t3 / 3;
    int qrow = 12 + q * 4 + i;
    int srow = s * 4 + j;
    const float* a = feat + (size_t)qrow * 4096;
    const float* c = feat + (size_t)srow * 4096;
    float p = 0.0f;
    for (int k = threadIdx.x; k < 4096; k += 128) p += a[k] * c[k];
    __shared__ float sm[128];
    sm[threadIdx.x] = p;
    __syncthreads();
    for (int o = 64; o > 0; o >>= 1) {
        if (threadIdx.x < o) sm[threadIdx.x] += sm[threadIdx.x + o];
        __syncthreads();
    }
    if (threadIdx.x == 0)
        cost[bi] = 1.0f - sm[0] / ((nrm[qrow] + 1e-8f) * (nrm[srow] + 1e-8f));
}

__global__ void sinkhorn_kernel(const float* __restrict__ cost, float* __restrict__ outp)
{
    int t = threadIdx.x;
    if (t >= 9) return;
    float sem[16], Km[16];
    for (int i = 0; i < 4; ++i)
        for (int j = 0; j < 4; ++j) {
            float sc = cost[t * 16 + i * 4 + j];
            float ti = i * 0.25f, tj = j * 0.25f;
            float d2 = (ti - tj) * (ti - tj);
            float pos = expf(-1.0f / (d2 + 1.0f));
            sem[i * 4 + j] = sc;
            Km[i * 4 + j] = expf(-7.0f * (sc + 0.4f * pos));
        }
    float u[4] = {0.25f, 0.25f, 0.25f, 0.25f}, v[4];
    for (int it = 0; it < 100; ++it) {
        for (int j = 0; j < 4; ++j) {
            float s = 1e-9f;
            for (int i = 0; i < 4; ++i) s += Km[i * 4 + j] * u[i];
            v[j] = 0.25f / s;
        }
        for (int i = 0; i < 4; ++i) {
            float s = 1e-9f;
            for (int j = 0; j < 4; ++j) s += Km[i * 4 + j] * v[j];
            u[i] = 0.25f / s;
        }
    }
    for (int j = 0; j < 4; ++j) {
        float s = 1e-9f;
        for (int i = 0; i < 4; ++i) s += Km[i * 4 + j] * u[i];
        v[j] = 0.25f / s;
    }
    float tr = 0.0f;
    for (int i = 0; i < 4; ++i)
        for (int j = 0; j < 4; ++j)
            tr += u[i] * Km[i * 4 + j] * v[j] * sem[i * 4 + j];
    outp[t] = -tr;
}

// ---------------------------------------------------------------------------
// Driver
// ---------------------------------------------------------------------------
static inline int cdiv_i(long a, long b) { return (int)((a + b - 1) / b); }

extern "C" void kernel_launch(void* const* d_in, const int* in_sizes, int n_in,
                              void* d_out, int out_size)
{
    const float* sup  = (const float*)d_in[0];
    const float* qry  = (const float*)d_in[1];
    const float* w1   = (const float*)d_in[2];
    const float* b1   = (const float*)d_in[3];
    const float* w2   = (const float*)d_in[4];
    const float* b2   = (const float*)d_in[5];
    const float* w3a  = (const float*)d_in[6];
    const float* b3a  = (const float*)d_in[7];
    const float* w3b  = (const float*)d_in[8];
    const float* b3b  = (const float*)d_in[9];
    const float* w4a  = (const float*)d_in[10];
    const float* b4a  = (const float*)d_in[11];
    const float* w4b  = (const float*)d_in[12];
    const float* b4b  = (const float*)d_in[13];
    const float* w5a  = (const float*)d_in[14];
    const float* b5a  = (const float*)d_in[15];
    const float* w5b  = (const float*)d_in[16];
    const float* b5b  = (const float*)d_in[17];
    const float* fw6  = (const float*)d_in[18];
    const float* fb6  = (const float*)d_in[19];
    const float* fw7  = (const float*)d_in[20];
    const float* fb7  = (const float*)d_in[21];

    float *pad, *act, *feat, *fc6o, *fc7o, *nrm, *cst, *w1p;
    cudaGetSymbolAddress((void**)&pad,  g_pad);
    cudaGetSymbolAddress((void**)&act,  g_act);
    cudaGetSymbolAddress((void**)&feat, g_feat);
    cudaGetSymbolAddress((void**)&fc6o, g_fc6);
    cudaGetSymbolAddress((void**)&fc7o, g_fc7);
    cudaGetSymbolAddress((void**)&nrm,  g_norm);
    cudaGetSymbolAddress((void**)&cst,  g_cost);
    cudaGetSymbolAddress((void**)&w1p,  g_w1);

    const float SC = BN_SCALE_F;

    // input rearrange + pad -> [24][3][18][114][114]
    rearrange_pad_kernel<<<dim3(cdiv_i(18 * 114 * 114, 256), 72), 256>>>(sup, qry, pad);
    w1prep_kernel<<<cdiv_i(64 * 96, 256), 256>>>(w1, w1p);

    // conv1: 3->64, (16,112,112), K 81->96
    conv_gemm<64><<<dim3(37632, 1), 256>>>(w1p, pad, act, b1, SC,
                                           3, 16, 112, 112, 81, 96, 64, 4816896);
    // pool1 (1,2,2) + pad -> [24][64][18][58][58]
    pool_pad_kernel<<<dim3(cdiv_i(18 * 58 * 58, 256), 24 * 64), 256>>>(
        act, pad, 16, 112, 112, 1, 2, 2, 1, 2, 2, 0, 0, 0, 16, 56, 56, 1);
    // conv2: 64->128, (16,56,56)
    conv_gemm<128><<<dim3(9408, 1), 256>>>(w2, pad, act, b2, SC,
                                           64, 16, 56, 56, 1728, 1728, 128, 1204224);
    // pool2 (2,2,2) + pad -> [24][128][10][30][30]
    pool_pad_kernel<<<dim3(cdiv_i(10 * 30 * 30, 256), 24 * 128), 256>>>(
        act, pad, 16, 56, 56, 2, 2, 2, 2, 2, 2, 0, 0, 0, 8, 28, 28, 1);
    // conv3a: 128->256, (8,28,28), no BN scale
    conv_gemm<128><<<dim3(1176, 2), 256>>>(w3a, pad, act, b3a, 1.0f,
                                           128, 8, 28, 28, 3456, 3456, 256, 150528);
    // identity pad -> [24][256][10][30][30]
    pool_pad_kernel<<<dim3(cdiv_i(10 * 30 * 30, 256), 24 * 256), 256>>>(
        act, pad, 8, 28, 28, 1, 1, 1, 1, 1, 1, 0, 0, 0, 8, 28, 28, 1);
    // conv3b: 256->256
    conv_gemm<128><<<dim3(1176, 2), 256>>>(w3b, pad, act, b3b, SC,
                                           256, 8, 28, 28, 6912, 6912, 256, 150528);
    // pool3 -> [24][256][6][16][16]
    pool_pad_kernel<<<dim3(cdiv_i(6 * 16 * 16, 256), 24 * 256), 256>>>(
        act, pad, 8, 28, 28, 2, 2, 2, 2, 2, 2, 0, 0, 0, 4, 14, 14, 1);
    // conv4a: 256->512, (4,14,14), no BN scale
    conv_gemm<128><<<dim3(147, 4), 256>>>(w4a, pad, act, b4a, 1.0f,
                                          256, 4, 14, 14, 6912, 6912, 512, 18816);
    // identity pad -> [24][512][6][16][16]
    pool_pad_kernel<<<dim3(cdiv_i(6 * 16 * 16, 256), 24 * 512), 256>>>(
        act, pad, 4, 14, 14, 1, 1, 1, 1, 1, 1, 0, 0, 0, 4, 14, 14, 1);
    // conv4b: 512->512
    conv_gemm<128><<<dim3(147, 4), 256>>>(w4b, pad, act, b4b, SC,
                                          512, 4, 14, 14, 13824, 13824, 512, 18816);
    // pool4 -> [24][512][4][9][9]
    pool_pad_kernel<<<dim3(cdiv_i(4 * 9 * 9, 256), 24 * 512), 256>>>(
        act, pad, 4, 14, 14, 2, 2, 2, 2, 2, 2, 0, 0, 0, 2, 7, 7, 1);
    // conv5a: 512->512, (2,7,7), no BN scale  (BM=64 for occupancy: 19x8=152 blocks)
    conv_gemm<64><<<dim3(19, 8), 256>>>(w5a, pad, act, b5a, 1.0f,
                                        512, 2, 7, 7, 13824, 13824, 512, 2352);
    // identity pad -> [24][512][4][9][9]
    pool_pad_kernel<<<dim3(cdiv_i(4 * 9 * 9, 256), 24 * 512), 256>>>(
        act, pad, 2, 7, 7, 1, 1, 1, 1, 1, 1, 0, 0, 0, 2, 7, 7, 1);
    // conv5b: 512->512
    conv_gemm<64><<<dim3(19, 8), 256>>>(w5b, pad, act, b5b, SC,
                                        512, 2, 7, 7, 13824, 13824, 512, 2352);
    // pool5 (2,2,2) pad(0,1,1) -> features [24][8192]
    pool_pad_kernel<<<dim3(1, 24 * 512), 256>>>(
        act, feat, 2, 7, 7, 2, 2, 2, 2, 2, 2, 0, 1, 1, 1, 4, 4, 0);
    // fc6, fc7
    fc_relu_kernel<<<cdiv_i(4096 * 24, 256), 256>>>(feat, fw6, fb6, fc6o, 8192, 4096, 24, SC);
    fc_relu_kernel<<<cdiv_i(4096 * 24, 256), 256>>>(fc6o, fw7, fb7, fc7o, 4096, 4096, 24, SC);

    // head
    rownorm_kernel<<<24, 128>>>(fc7o, nrm, 4096);
    cost_kernel<<<144, 128>>>(fc7o, nrm, cst);
    sinkhorn_kernel<<<1, 32>>>(cst, (float*)d_out);
}

// round 5
// speedup vs baseline: 1.0793x; 1.0001x over previous
#include <cuda_runtime.h>
#include <math.h>

#define BN_SCALE_F 0.9999950000374996f  // 1/sqrt(1+1e-5)

// ---------------------------------------------------------------------------
// Static device scratch
// ---------------------------------------------------------------------------
__device__ float g_pad[93007872];    // max padded input: conv2 in 24*64*18*58*58
__device__ float g_act[308281344];   // max conv out: conv1 out 24*64*16*112*112
__device__ float g_feat[24 * 8192];
__device__ float g_fc6[24 * 4096];
__device__ float g_fc7[24 * 4096];
__device__ float g_norm[24];
__device__ float g_cost[144];
__device__ float g_w1[64 * 96];      // conv1 weights K-padded 81->96

// ---------------------------------------------------------------------------
// Packed fp32x2 helpers (Blackwell native; 2x fp32 FMA throughput)
// ---------------------------------------------------------------------------
__device__ __forceinline__ void ffma2(unsigned long long& d,
                                      unsigned long long a,
                                      unsigned long long b)
{
    asm("fma.rn.f32x2 %0, %1, %2, %0;" : "+l"(d) : "l"(a), "l"(b));
}
__device__ __forceinline__ unsigned long long splat2(float x)
{
    unsigned long long r;
    asm("mov.b64 %0, {%1, %1};" : "=l"(r) : "f"(x));
    return r;
}
__device__ __forceinline__ void unpack2(unsigned long long p, float& lo, float& hi)
{
    asm("mov.b64 {%0, %1}, %2;" : "=f"(lo), "=f"(hi) : "l"(p));
}

// ---------------------------------------------------------------------------
// Rearrange raw inputs -> padded clips [24][3][18][114][114]
// grid.y = clip*3 + c  (72 planes); grid.x covers 18*114*114
// ---------------------------------------------------------------------------
__global__ void rearrange_pad_kernel(const float* __restrict__ sup,
                                     const float* __restrict__ qry,
                                     float* __restrict__ out)
{
    const int plane = blockIdx.y;          // clip*3 + c
    const int clip = plane / 3;
    const int c = plane - clip * 3;
    const int s = blockIdx.x * blockDim.x + threadIdx.x;
    const int HWp = 114 * 114;
    if (s >= 18 * HWp) return;
    int dz = s / HWp;
    int r = s - dz * HWp;
    int hy = r / 114;
    int wx = r - hy * 114;
    float val = 0.0f;
    if (dz >= 1 && dz <= 16 && hy >= 1 && hy <= 112 && wx >= 1 && wx <= 112) {
        int tt = dz - 1, h = hy - 1, w = wx - 1;
        const float* src = (clip < 12) ? sup : qry;
        int cc = (clip < 12) ? clip : clip - 12;
        long addr = ((((long)cc * 16 + tt) * 3 + c) * 112 + h) * 112 + w;
        val = src[addr];
    }
    out[(long)plane * 18 * HWp + s] = val;
}

// conv1 weight prep: [64][81] -> [64][96] zero-padded along K
__global__ void w1prep_kernel(const float* __restrict__ w, float* __restrict__ out)
{
    int idx = blockIdx.x * blockDim.x + threadIdx.x;
    if (idx >= 64 * 96) return;
    int m = idx / 96, k = idx - m * 96;
    out[idx] = (k < 81) ? w[m * 81 + k] : 0.0f;
}

// ---------------------------------------------------------------------------
// Implicit-GEMM conv3d using packed f32x2 FMAs.
//   A: weights [Cout][Kpad].  inp: padded [B][Cin][D+2][H+2][W+2]
//   out: [B][Cout][D][H][W] = relu(scale * (conv + bias))
// ---------------------------------------------------------------------------
template <int BM>
__global__ __launch_bounds__(256, 2)
void conv_gemm(const float* __restrict__ A, const float* __restrict__ inp,
               float* __restrict__ out, const float* __restrict__ bias, float scale,
               int Cin, int D, int H, int W, int Ktrue, int Kpad, int Cout, int Ntotal)
{
    constexpr int BNt = 128, BK = 16;
    constexpr int MR = (BM == 128) ? 8 : 4;
    const int Hp = H + 2, Wp = W + 2;
    const int HWp = Hp * Wp;
    const int chanStride = (D + 2) * HWp;
    const int HW = H * W;
    const int DHW = D * HW;

    __shared__ float sA[2][BK][BM];
    __shared__ float sB[2][BK][BNt];

    const int tid = threadIdx.x;
    const int tx = tid & 15;
    const int ty = tid >> 4;
    const int ntile = blockIdx.x;
    const int mtile = blockIdx.y;

    // ---- B-tile load mapping ----
    const int krow = ty;
    const int n0 = tx * 8;
    int nbase[8];
#pragma unroll
    for (int j = 0; j < 8; ++j) {
        int n = ntile * BNt + n0 + j;
        if (n >= Ntotal) n = Ntotal - 1;
        int b = n / DHW;
        int rem = n - b * DHW;
        int d = rem / HW;
        int r2 = rem - d * HW;
        int h = r2 / W;
        int w = r2 - h * W;
        nbase[j] = b * Cin * chanStride + d * HWp + h * Wp + w;
    }

    // ---- A-tile load mapping ----
    const int am = tid & (BM - 1);
    const int akg = tid / BM;
    const float* Aptr = A + (size_t)(mtile * BM + am) * Kpad;

    float4 stA0, stA1;
    float stB[8];
    int koff = 0;

    auto LOADK = [&](int k0_) {
        if constexpr (BM == 128) {
            stA0 = *(const float4*)(Aptr + k0_ + akg * 8);
            stA1 = *(const float4*)(Aptr + k0_ + akg * 8 + 4);
        } else {
            stA0 = *(const float4*)(Aptr + k0_ + akg * 4);
        }
        int kg_ = k0_ + krow;
        int ke_ = (kg_ < Ktrue) ? kg_ : 0;
        int ci_ = ke_ / 27;
        int r_ = ke_ - ci_ * 27;
        int kd_ = r_ / 9; r_ -= kd_ * 9;
        int kh_ = r_ / 3;
        int kw_ = r_ - kh_ * 3;
        koff = ci_ * chanStride + kd_ * HWp + kh_ * Wp + kw_;
#pragma unroll
        for (int j = 0; j < 8; ++j) stB[j] = __ldg(inp + nbase[j] + koff);
    };

    auto STORETILE = [&](int bf_) {
        if constexpr (BM == 128) {
            int kb_ = akg * 8;
            sA[bf_][kb_ + 0][am] = stA0.x;
            sA[bf_][kb_ + 1][am] = stA0.y;
            sA[bf_][kb_ + 2][am] = stA0.z;
            sA[bf_][kb_ + 3][am] = stA0.w;
            sA[bf_][kb_ + 4][am] = stA1.x;
            sA[bf_][kb_ + 5][am] = stA1.y;
            sA[bf_][kb_ + 6][am] = stA1.z;
            sA[bf_][kb_ + 7][am] = stA1.w;
        } else {
            int kb_ = akg * 4;
            sA[bf_][kb_ + 0][am] = stA0.x;
            sA[bf_][kb_ + 1][am] = stA0.y;
            sA[bf_][kb_ + 2][am] = stA0.z;
            sA[bf_][kb_ + 3][am] = stA0.w;
        }
        *(float4*)&sB[bf_][krow][n0]     = make_float4(stB[0], stB[1], stB[2], stB[3]);
        *(float4*)&sB[bf_][krow][n0 + 4] = make_float4(stB[4], stB[5], stB[6], stB[7]);
    };

    // Packed accumulators: acc2[i][jp] = (col 2jp, col 2jp+1) pair
    unsigned long long acc2[MR][4];
#pragma unroll
    for (int i = 0; i < MR; ++i)
#pragma unroll
        for (int jp = 0; jp < 4; ++jp) acc2[i][jp] = 0ULL;

    const int KT = Kpad / BK;

    LOADK(0);
    STORETILE(0);
    __syncthreads();

    for (int kt = 0; kt < KT; ++kt) {
        int buf = kt & 1;
        if (kt + 1 < KT) LOADK((kt + 1) * BK);
#pragma unroll
        for (int kk = 0; kk < BK; ++kk) {
            // B pairs: 16B loads reinterpreted as 2x packed f32x2
            ulonglong2 b0 = *(const ulonglong2*)&sB[buf][kk][tx * 4];
            ulonglong2 b1 = *(const ulonglong2*)&sB[buf][kk][64 + tx * 4];
            unsigned long long bp[4] = {b0.x, b0.y, b1.x, b1.y};
            float af[MR];
            float4 a0 = *(const float4*)&sA[buf][kk][ty * 4];
            af[0] = a0.x; af[1] = a0.y; af[2] = a0.z; af[3] = a0.w;
            if constexpr (BM == 128) {
                float4 a1 = *(const float4*)&sA[buf][kk][64 + ty * 4];
                af[4] = a1.x; af[5] = a1.y; af[6] = a1.z; af[7] = a1.w;
            }
#pragma unroll
            for (int i = 0; i < MR; ++i) {
                unsigned long long a2 = splat2(af[i]);
                ffma2(acc2[i][0], a2, bp[0]);
                ffma2(acc2[i][1], a2, bp[1]);
                ffma2(acc2[i][2], a2, bp[2]);
                ffma2(acc2[i][3], a2, bp[3]);
            }
        }
        if (kt + 1 < KT) STORETILE(buf ^ 1);
        __syncthreads();
    }

    // ---- epilogue: bias + scale + relu, scatter to NCDHW ----
#pragma unroll
    for (int jp = 0; jp < 4; ++jp) {
        // jp 0,1 -> cols tx*4 + {0,1},{2,3}; jp 2,3 -> cols 64+tx*4 + {0,1},{2,3}
        int colbase = (jp < 2) ? (tx * 4 + jp * 2) : (64 + tx * 4 + (jp - 2) * 2);
#pragma unroll
        for (int half = 0; half < 2; ++half) {
            int n = ntile * BNt + colbase + half;
            if (n >= Ntotal) continue;
            int b = n / DHW;
            int rem = n - b * DHW;
            size_t obase = ((size_t)b * Cout) * DHW + rem;
#pragma unroll
            for (int i = 0; i < MR; ++i) {
                int row = (i < 4) ? (ty * 4 + i) : (64 + ty * 4 + i - 4);
                int m = mtile * BM + row;
                float lo, hi;
                unpack2(acc2[i][jp], lo, hi);
                float v = scale * (((half == 0) ? lo : hi) + bias[m]);
                out[obase + (size_t)m * DHW] = fmaxf(v, 0.0f);
            }
        }
    }
}

// ---------------------------------------------------------------------------
// Fused maxpool + conv-halo-pad. grid.y = b*C + c (plane); 32-bit indexing.
// Writes [plane][Do+2cp][Ho+2cp][Wo+2cp]. Identity pool (k=s=1) = pure pad.
// ---------------------------------------------------------------------------
__global__ void pool_pad_kernel(const float* __restrict__ in, float* __restrict__ out,
                                int D, int H, int W,
                                int kd, int kh, int kw, int sd, int sh, int sw,
                                int pd, int ph, int pw,
                                int Do, int Ho, int Wo, int cp)
{
    const int plane = blockIdx.y;
    const int Hp = Ho + 2 * cp, Wp = Wo + 2 * cp, Dp = Do + 2 * cp;
    const int HWp = Hp * Wp;
    const int s = blockIdx.x * blockDim.x + threadIdx.x;
    if (s >= Dp * HWp) return;
    int z = s / HWp;
    int r = s - z * HWp;
    int y = r / Wp;
    int x = r - y * Wp;
    float v = 0.0f;
    int od = z - cp, oh = y - cp, ow = x - cp;
    if (od >= 0 && od < Do && oh >= 0 && oh < Ho && ow >= 0 && ow < Wo) {
        float m = -3.4e38f;
        int id0 = od * sd - pd, ih0 = oh * sh - ph, iw0 = ow * sw - pw;
        const float* base = in + (long)plane * D * H * W;
        for (int a = 0; a < kd; ++a) {
            int id = id0 + a;
            if (id < 0 || id >= D) continue;
            for (int e = 0; e < kh; ++e) {
                int ih = ih0 + e;
                if (ih < 0 || ih >= H) continue;
                for (int f = 0; f < kw; ++f) {
                    int iw = iw0 + f;
                    if (iw < 0 || iw >= W) continue;
                    float q = base[(id * H + ih) * W + iw];
                    m = fmaxf(m, q);
                }
            }
        }
        v = m;
    }
    out[(long)plane * Dp * HWp + s] = v;
}

// ---------------------------------------------------------------------------
// FC: y[n][m] = relu(scale * (x[n] . W[m] + b[m]))
// ---------------------------------------------------------------------------
__global__ void fc_relu_kernel(const float* __restrict__ x, const float* __restrict__ W,
                               const float* __restrict__ b, float* __restrict__ y,
                               int K, int M, int N, float scale)
{
    int idx = blockIdx.x * blockDim.x + threadIdx.x;
    if (idx >= M * N) return;
    int m = idx / N;
    int n = idx - m * N;
    const float4* wr = (const float4*)(W + (size_t)m * K);
    const float4* xr = (const float4*)(x + (size_t)n * K);
    float s = 0.0f;
    int K4 = K >> 2;
#pragma unroll 4
    for (int k = 0; k < K4; ++k) {
        float4 a = wr[k];
        float4 c = xr[k];
        s += a.x * c.x + a.y * c.y + a.z * c.z + a.w * c.w;
    }
    float v = scale * (s + b[m]);
    y[(size_t)n * M + m] = fmaxf(v, 0.0f);
}

__global__ void rownorm_kernel(const float* __restrict__ x, float* __restrict__ nrm, int K)
{
    int row = blockIdx.x;
    float s = 0.0f;
    for (int k = threadIdx.x; k < K; k += 128) {
        float v = x[(size_t)row * K + k];
        s += v * v;
    }
    __shared__ float sm[128];
    sm[threadIdx.x] = s;
    __syncthreads();
    for (int o = 64; o > 0; o >>= 1) {
        if (threadIdx.x < o) sm[threadIdx.x] += sm[threadIdx.x + o];
        __syncthreads();
    }
    if (threadIdx.x == 0) nrm[row] = sqrtf(sm[0]);
}

__global__ void cost_kernel(const float* __restrict__ feat, const float* __restrict__ nrm,
                            float* __restrict__ cost)
{
    int bi = blockIdx.x;  // ((q*3+s)*4+i)*4+j
    int j = bi & 3, t2 = bi >> 2;
    int i = t2 & 3, t3 = t2 >> 2;
    int s = t3 % 3, q = t3 / 3;
    int qrow = 12 + q * 4 + i;
    int srow = s * 4 + j;
    const float* a = feat + (size_t)qrow * 4096;
    const float* c = feat + (size_t)srow * 4096;
    float p = 0.0f;
    for (int k = threadIdx.x; k < 4096; k += 128) p += a[k] * c[k];
    __shared__ float sm[128];
    sm[threadIdx.x] = p;
    __syncthreads();
    for (int o = 64; o > 0; o >>= 1) {
        if (threadIdx.x < o) sm[threadIdx.x] += sm[threadIdx.x + o];
        __syncthreads();
    }
    if (threadIdx.x == 0)
        cost[bi] = 1.0f - sm[0] / ((nrm[qrow] + 1e-8f) * (nrm[srow] + 1e-8f));
}

__global__ void sinkhorn_kernel(const float* __restrict__ cost, float* __restrict__ outp)
{
    int t = threadIdx.x;
    if (t >= 9) return;
    float sem[16], Km[16];
    for (int i = 0; i < 4; ++i)
        for (int j = 0; j < 4; ++j) {
            float sc = cost[t * 16 + i * 4 + j];
            float ti = i * 0.25f, tj = j * 0.25f;
            float d2 = (ti - tj) * (ti - tj);
            float pos = expf(-1.0f / (d2 + 1.0f));
            sem[i * 4 + j] = sc;
            Km[i * 4 + j] = expf(-7.0f * (sc + 0.4f * pos));
        }
    float u[4] = {0.25f, 0.25f, 0.25f, 0.25f}, v[4];
    for (int it = 0; it < 100; ++it) {
        for (int j = 0; j < 4; ++j) {
            float s = 1e-9f;
            for (int i = 0; i < 4; ++i) s += Km[i * 4 + j] * u[i];
            v[j] = 0.25f / s;
        }
        for (int i = 0; i < 4; ++i) {
            float s = 1e-9f;
            for (int j = 0; j < 4; ++j) s += Km[i * 4 + j] * v[j];
            u[i] = 0.25f / s;
        }
    }
    for (int j = 0; j < 4; ++j) {
        float s = 1e-9f;
        for (int i = 0; i < 4; ++i) s += Km[i * 4 + j] * u[i];
        v[j] = 0.25f / s;
    }
    float tr = 0.0f;
    for (int i = 0; i < 4; ++i)
        for (int j = 0; j < 4; ++j)
            tr += u[i] * Km[i * 4 + j] * v[j] * sem[i * 4 + j];
    outp[t] = -tr;
}

// ---------------------------------------------------------------------------
// Driver
// ---------------------------------------------------------------------------
static inline int cdiv_i(long a, long b) { return (int)((a + b - 1) / b); }

extern "C" void kernel_launch(void* const* d_in, const int* in_sizes, int n_in,
                              void* d_out, int out_size)
{
    const float* sup  = (const float*)d_in[0];
    const float* qry  = (const float*)d_in[1];
    const float* w1   = (const float*)d_in[2];
    const float* b1   = (const float*)d_in[3];
    const float* w2   = (const float*)d_in[4];
    const float* b2   = (const float*)d_in[5];
    const float* w3a  = (const float*)d_in[6];
    const float* b3a  = (const float*)d_in[7];
    const float* w3b  = (const float*)d_in[8];
    const float* b3b  = (const float*)d_in[9];
    const float* w4a  = (const float*)d_in[10];
    const float* b4a  = (const float*)d_in[11];
    const float* w4b  = (const float*)d_in[12];
    const float* b4b  = (const float*)d_in[13];
    const float* w5a  = (const float*)d_in[14];
    const float* b5a  = (const float*)d_in[15];
    const float* w5b  = (const float*)d_in[16];
    const float* b5b  = (const float*)d_in[17];
    const float* fw6  = (const float*)d_in[18];
    const float* fb6  = (const float*)d_in[19];
    const float* fw7  = (const float*)d_in[20];
    const float* fb7  = (const float*)d_in[21];

    float *pad, *act, *feat, *fc6o, *fc7o, *nrm, *cst, *w1p;
    cudaGetSymbolAddress((void**)&pad,  g_pad);
    cudaGetSymbolAddress((void**)&act,  g_act);
    cudaGetSymbolAddress((void**)&feat, g_feat);
    cudaGetSymbolAddress((void**)&fc6o, g_fc6);
    cudaGetSymbolAddress((void**)&fc7o, g_fc7);
    cudaGetSymbolAddress((void**)&nrm,  g_norm);
    cudaGetSymbolAddress((void**)&cst,  g_cost);
    cudaGetSymbolAddress((void**)&w1p,  g_w1);

    const float SC = BN_SCALE_F;

    // input rearrange + pad -> [24][3][18][114][114]
    rearrange_pad_kernel<<<dim3(cdiv_i(18 * 114 * 114, 256), 72), 256>>>(sup, qry, pad);
    w1prep_kernel<<<cdiv_i(64 * 96, 256), 256>>>(w1, w1p);

    // conv1: 3->64, (16,112,112), K 81->96
    conv_gemm<64><<<dim3(37632, 1), 256>>>(w1p, pad, act, b1, SC,
                                           3, 16, 112, 112, 81, 96, 64, 4816896);
    // pool1 (1,2,2) + pad -> [24][64][18][58][58]
    pool_pad_kernel<<<dim3(cdiv_i(18 * 58 * 58, 256), 24 * 64), 256>>>(
        act, pad, 16, 112, 112, 1, 2, 2, 1, 2, 2, 0, 0, 0, 16, 56, 56, 1);
    // conv2: 64->128, (16,56,56)
    conv_gemm<128><<<dim3(9408, 1), 256>>>(w2, pad, act, b2, SC,
                                           64, 16, 56, 56, 1728, 1728, 128, 1204224);
    // pool2 (2,2,2) + pad -> [24][128][10][30][30]
    pool_pad_kernel<<<dim3(cdiv_i(10 * 30 * 30, 256), 24 * 128), 256>>>(
        act, pad, 16, 56, 56, 2, 2, 2, 2, 2, 2, 0, 0, 0, 8, 28, 28, 1);
    // conv3a: 128->256, (8,28,28), no BN scale
    conv_gemm<128><<<dim3(1176, 2), 256>>>(w3a, pad, act, b3a, 1.0f,
                                           128, 8, 28, 28, 3456, 3456, 256, 150528);
    // identity pad -> [24][256][10][30][30]
    pool_pad_kernel<<<dim3(cdiv_i(10 * 30 * 30, 256), 24 * 256), 256>>>(
        act, pad, 8, 28, 28, 1, 1, 1, 1, 1, 1, 0, 0, 0, 8, 28, 28, 1);
    // conv3b: 256->256
    conv_gemm<128><<<dim3(1176, 2), 256>>>(w3b, pad, act, b3b, SC,
                                           256, 8, 28, 28, 6912, 6912, 256, 150528);
    // pool3 -> [24][256][6][16][16]
    pool_pad_kernel<<<dim3(cdiv_i(6 * 16 * 16, 256), 24 * 256), 256>>>(
        act, pad, 8, 28, 28, 2, 2, 2, 2, 2, 2, 0, 0, 0, 4, 14, 14, 1);
    // conv4a: 256->512, (4,14,14), no BN scale
    conv_gemm<128><<<dim3(147, 4), 256>>>(w4a, pad, act, b4a, 1.0f,
                                          256, 4, 14, 14, 6912, 6912, 512, 18816);
    // identity pad -> [24][512][6][16][16]
    pool_pad_kernel<<<dim3(cdiv_i(6 * 16 * 16, 256), 24 * 512), 256>>>(
        act, pad, 4, 14, 14, 1, 1, 1, 1, 1, 1, 0, 0, 0, 4, 14, 14, 1);
    // conv4b: 512->512
    conv_gemm<128><<<dim3(147, 4), 256>>>(w4b, pad, act, b4b, SC,
                                          512, 4, 14, 14, 13824, 13824, 512, 18816);
    // pool4 -> [24][512][4][9][9]
    pool_pad_kernel<<<dim3(cdiv_i(4 * 9 * 9, 256), 24 * 512), 256>>>(
        act, pad, 4, 14, 14, 2, 2, 2, 2, 2, 2, 0, 0, 0, 2, 7, 7, 1);
    // conv5a: 512->512, (2,7,7), no BN scale  (BM=64 for occupancy: 19x8=152 blocks)
    conv_gemm<64><<<dim3(19, 8), 256>>>(w5a, pad, act, b5a, 1.0f,
                                        512, 2, 7, 7, 13824, 13824, 512, 2352);
    // identity pad -> [24][512][4][9][9]
    pool_pad_kernel<<<dim3(cdiv_i(4 * 9 * 9, 256), 24 * 512), 256>>>(
        act, pad, 2, 7, 7, 1, 1, 1, 1, 1, 1, 0, 0, 0, 2, 7, 7, 1);
    // conv5b: 512->512
    conv_gemm<64><<<dim3(19, 8), 256>>>(w5b, pad, act, b5b, SC,
                                        512, 2, 7, 7, 13824, 13824, 512, 2352);
    // pool5 (2,2,2) pad(0,1,1) -> features [24][8192]
    pool_pad_kernel<<<dim3(1, 24 * 512), 256>>>(
        act, feat, 2, 7, 7, 2, 2, 2, 2, 2, 2, 0, 1, 1, 1, 4, 4, 0);
    // fc6, fc7
    fc_relu_kernel<<<cdiv_i(4096 * 24, 256), 256>>>(feat, fw6, fb6, fc6o, 8192, 4096, 24, SC);
    fc_relu_kernel<<<cdiv_i(4096 * 24, 256), 256>>>(fc6o, fw7, fb7, fc7o, 4096, 4096, 24, SC);

    // head
    rownorm_kernel<<<24, 128>>>(fc7o, nrm, 4096);
    cost_kernel<<<144, 128>>>(fc7o, nrm, cst);
    sinkhorn_kernel<<<1, 32>>>(cst, (float*)d_out);
}

// round 8
// speedup vs baseline: 1.5203x; 1.4086x over previous
#include <cuda_runtime.h>
#include <cuda_bf16.h>
#include <mma.h>
#include <math.h>
#include <stdint.h>

using namespace nvcuda;

#define BN_SCALE_F 0.9999950000374996f

// ---------------- static scratch ----------------
__device__ float g_pad[93007872];
__device__ float g_act[308281344];
__device__ float g_feat[24 * 8192];
__device__ float g_fc6[24 * 4096];
__device__ float g_fc7[24 * 4096];
__device__ float g_norm[24];
__device__ float g_cost[144];
__device__ float g_w1[64 * 96];
__device__ unsigned g_wpk[27648000];   // packed split weights conv2..conv5b

// ---------------- helpers ----------------
__device__ __forceinline__ unsigned pack_split(float v) {
    float hf = __uint_as_float(__float_as_uint(v) & 0xFFFF0000u);  // truncate-to-bf16 hi
    unsigned hi = __float_as_uint(hf) >> 16;
    float r = v - hf;
    unsigned lo = __float_as_uint(r) >> 16;                        // truncated lo
    return hi | (lo << 16);
}
__device__ __forceinline__ void ffma2(unsigned long long& d, unsigned long long a, unsigned long long b) {
    asm("fma.rn.f32x2 %0, %1, %2, %0;" : "+l"(d) : "l"(a), "l"(b));
}
__device__ __forceinline__ unsigned long long splat2(float x) {
    unsigned long long r;
    asm("mov.b64 %0, {%1, %1};" : "=l"(r) : "f"(x));
    return r;
}
__device__ __forceinline__ void unpack2(unsigned long long p, float& lo, float& hi) {
    asm("mov.b64 {%0, %1}, %2;" : "=f"(lo), "=f"(hi) : "l"(p));
}

// ---------------- input rearrange + pad (fp32) ----------------
__global__ void rearrange_pad_kernel(const float* __restrict__ sup, const float* __restrict__ qry,
                                     float* __restrict__ out)
{
    const int plane = blockIdx.y;
    const int clip = plane / 3;
    const int c = plane - clip * 3;
    const int s = blockIdx.x * blockDim.x + threadIdx.x;
    const int HWp = 114 * 114;
    if (s >= 18 * HWp) return;
    int dz = s / HWp;
    int r = s - dz * HWp;
    int hy = r / 114;
    int wx = r - hy * 114;
    float val = 0.0f;
    if (dz >= 1 && dz <= 16 && hy >= 1 && hy <= 112 && wx >= 1 && wx <= 112) {
        int tt = dz - 1, h = hy - 1, w = wx - 1;
        const float* src = (clip < 12) ? sup : qry;
        int cc = (clip < 12) ? clip : clip - 12;
        long addr = ((((long)cc * 16 + tt) * 3 + c) * 112 + h) * 112 + w;
        val = src[addr];
    }
    out[(long)plane * 18 * HWp + s] = val;
}

__global__ void w1prep_kernel(const float* __restrict__ w, float* __restrict__ out)
{
    int idx = blockIdx.x * blockDim.x + threadIdx.x;
    if (idx >= 64 * 96) return;
    int m = idx / 96, k = idx - m * 96;
    out[idx] = (k < 81) ? w[m * 81 + k] : 0.0f;
}

__global__ void wpack_kernel(const float* __restrict__ w, unsigned* __restrict__ out, int n)
{
    int i = blockIdx.x * blockDim.x + threadIdx.x;
    if (i < n) out[i] = pack_split(w[i]);
}

// ---------------- conv1: SIMT implicit GEMM (fp32, f32x2 FMA) ----------------
__global__ __launch_bounds__(256, 2)
void conv_gemm(const float* __restrict__ A, const float* __restrict__ inp,
               float* __restrict__ out, const float* __restrict__ bias, float scale,
               int Cin, int D, int H, int W, int Ktrue, int Kpad, int Cout, int Ntotal)
{
    constexpr int BM = 64, BNt = 128, BK = 16, MR = 4;
    const int Hp = H + 2, Wp = W + 2;
    const int HWp = Hp * Wp;
    const int chanStride = (D + 2) * HWp;
    const int HW = H * W;
    const int DHW = D * HW;

    __shared__ float sA[2][BK][BM];
    __shared__ float sB[2][BK][BNt];

    const int tid = threadIdx.x;
    const int tx = tid & 15;
    const int ty = tid >> 4;
    const int ntile = blockIdx.x;
    const int mtile = blockIdx.y;

    const int krow = ty;
    const int n0 = tx * 8;
    int nbase[8];
#pragma unroll
    for (int j = 0; j < 8; ++j) {
        int n = ntile * BNt + n0 + j;
        if (n >= Ntotal) n = Ntotal - 1;
        int b = n / DHW;
        int rem = n - b * DHW;
        int d = rem / HW;
        int r2 = rem - d * HW;
        int h = r2 / W;
        int w = r2 - h * W;
        nbase[j] = b * Cin * chanStride + d * HWp + h * Wp + w;
    }

    const int am = tid & (BM - 1);
    const int akg = tid / BM;
    const float* Aptr = A + (size_t)(mtile * BM + am) * Kpad;

    float4 stA0;
    float stB[8];
    int koff = 0;

    auto LOADK = [&](int k0_) {
        stA0 = *(const float4*)(Aptr + k0_ + akg * 4);
        int kg_ = k0_ + krow;
        int ke_ = (kg_ < Ktrue) ? kg_ : 0;
        int ci_ = ke_ / 27;
        int r_ = ke_ - ci_ * 27;
        int kd_ = r_ / 9; r_ -= kd_ * 9;
        int kh_ = r_ / 3;
        int kw_ = r_ - kh_ * 3;
        koff = ci_ * chanStride + kd_ * HWp + kh_ * Wp + kw_;
#pragma unroll
        for (int j = 0; j < 8; ++j) stB[j] = __ldg(inp + nbase[j] + koff);
    };
    auto STORETILE = [&](int bf_) {
        int kb_ = akg * 4;
        sA[bf_][kb_ + 0][am] = stA0.x;
        sA[bf_][kb_ + 1][am] = stA0.y;
        sA[bf_][kb_ + 2][am] = stA0.z;
        sA[bf_][kb_ + 3][am] = stA0.w;
        *(float4*)&sB[bf_][krow][n0]     = make_float4(stB[0], stB[1], stB[2], stB[3]);
        *(float4*)&sB[bf_][krow][n0 + 4] = make_float4(stB[4], stB[5], stB[6], stB[7]);
    };

    unsigned long long acc2[MR][4];
#pragma unroll
    for (int i = 0; i < MR; ++i)
#pragma unroll
        for (int jp = 0; jp < 4; ++jp) acc2[i][jp] = 0ULL;

    const int KT = Kpad / BK;
    LOADK(0);
    STORETILE(0);
    __syncthreads();

    for (int kt = 0; kt < KT; ++kt) {
        int buf = kt & 1;
        if (kt + 1 < KT) LOADK((kt + 1) * BK);
#pragma unroll
        for (int kk = 0; kk < BK; ++kk) {
            ulonglong2 b0 = *(const ulonglong2*)&sB[buf][kk][tx * 4];
            ulonglong2 b1 = *(const ulonglong2*)&sB[buf][kk][64 + tx * 4];
            unsigned long long bp[4] = {b0.x, b0.y, b1.x, b1.y};
            float4 a0 = *(const float4*)&sA[buf][kk][ty * 4];
            float af[MR] = {a0.x, a0.y, a0.z, a0.w};
#pragma unroll
            for (int i = 0; i < MR; ++i) {
                unsigned long long a2 = splat2(af[i]);
                ffma2(acc2[i][0], a2, bp[0]);
                ffma2(acc2[i][1], a2, bp[1]);
                ffma2(acc2[i][2], a2, bp[2]);
                ffma2(acc2[i][3], a2, bp[3]);
            }
        }
        if (kt + 1 < KT) STORETILE(buf ^ 1);
        __syncthreads();
    }

#pragma unroll
    for (int jp = 0; jp < 4; ++jp) {
        int colbase = (jp < 2) ? (tx * 4 + jp * 2) : (64 + tx * 4 + (jp - 2) * 2);
#pragma unroll
        for (int half = 0; half < 2; ++half) {
            int n = ntile * BNt + colbase + half;
            if (n >= Ntotal) continue;
            int b = n / DHW;
            int rem = n - b * DHW;
            size_t obase = ((size_t)b * Cout) * DHW + rem;
#pragma unroll
            for (int i = 0; i < MR; ++i) {
                int m = mtile * BM + ty * 4 + i;
                float lo, hi;
                unpack2(acc2[i][jp], lo, hi);
                float v = scale * (((half == 0) ? lo : hi) + bias[m]);
                out[obase + (size_t)m * DHW] = fmaxf(v, 0.0f);
            }
        }
    }
}

// ---------------- wmma split-bf16 conv (conv2..conv5b) ----------------
// GEMM: M=Cout (128/tile), N=spatial (128/tile), K chunks of 32.
// wpk: packed split weights [Cout][K]; inp: packed split padded acts; out fp32 NCDHW.
// smem tiles (per buffer): A_hi/A_lo [128][40] bf16, B_hi/B_lo [128][40] bf16.
#define TCA_HI 0
#define TCA_LO 10240
#define TCB_HI 20480
#define TCB_LO 30720
#define TCBUF  40960

__global__ __launch_bounds__(256)
void conv_tc(const unsigned* __restrict__ wpk, const unsigned* __restrict__ inp,
             float* __restrict__ out, const float* __restrict__ bias, float scale,
             int Cin, int D, int H, int W, int K, int Cout, int Ntotal)
{
    extern __shared__ char dsm[];
    char* albase = (char*)(((uintptr_t)dsm + 1023) & ~(uintptr_t)1023);

    const int Hp = H + 2, Wp = W + 2;
    const int HWp = Hp * Wp;
    const int chanStride = (D + 2) * HWp;
    const int HW = H * W;
    const int DHW = D * HW;

    const int t = threadIdx.x;
    const int wid = t >> 5;
    const int ntile = blockIdx.x;
    const int mtile = blockIdx.y;

    // ---- gather mapping: p = kpair (16), rbase = row (16), 8 row-slots/thread ----
    const int p = t & 15;
    const int rbase = t >> 4;
    int nb[8];
#pragma unroll
    for (int i = 0; i < 8; ++i) {
        int n = ntile * 128 + rbase + 16 * i;
        if (n >= Ntotal) n = Ntotal - 1;
        int b = n / DHW;
        int rem = n - b * DHW;
        int d = rem / HW;
        int r2 = rem - d * HW;
        int h = r2 / W;
        int w = r2 - h * W;
        nb[i] = b * Cin * chanStride + d * HWp + h * Wp + w;
    }
    const unsigned* Awp = wpk + (size_t)(mtile * 128 + rbase) * K + 2 * p;

    uint2 aw[8];
    uint32_t bw0[8], bw1[8];

    auto LOADC = [&](int k0) {
        int k = k0 + 2 * p;
        int ci = k / 27, r_ = k - ci * 27;
        int kd = r_ / 9; r_ -= kd * 9;
        int kh = r_ / 3, kw = r_ - kh * 3;
        const int ko0 = ci * chanStride + kd * HWp + kh * Wp + kw;
        ++k;
        ci = k / 27; r_ = k - ci * 27;
        kd = r_ / 9; r_ -= kd * 9;
        kh = r_ / 3; kw = r_ - kh * 3;
        const int ko1 = ci * chanStride + kd * HWp + kh * Wp + kw;
#pragma unroll
        for (int i = 0; i < 8; ++i) {
            aw[i] = *(const uint2*)(Awp + (size_t)(16 * i) * K + k0);
            bw0[i] = __ldg(inp + nb[i] + ko0);
            bw1[i] = __ldg(inp + nb[i] + ko1);
        }
    };
    auto STOREC = [&](char* sb) {
#pragma unroll
        for (int i = 0; i < 8; ++i) {
            int off = (rbase + 16 * i) * 80 + p * 4;
            uint32_t ahi, alo, bhi, blo;
            asm("prmt.b32 %0, %1, %2, 0x5410;" : "=r"(ahi) : "r"(aw[i].x), "r"(aw[i].y));
            asm("prmt.b32 %0, %1, %2, 0x7632;" : "=r"(alo) : "r"(aw[i].x), "r"(aw[i].y));
            asm("prmt.b32 %0, %1, %2, 0x5410;" : "=r"(bhi) : "r"(bw0[i]), "r"(bw1[i]));
            asm("prmt.b32 %0, %1, %2, 0x7632;" : "=r"(blo) : "r"(bw0[i]), "r"(bw1[i]));
            *(uint32_t*)(sb + TCA_HI + off) = ahi;
            *(uint32_t*)(sb + TCA_LO + off) = alo;
            *(uint32_t*)(sb + TCB_HI + off) = bhi;
            *(uint32_t*)(sb + TCB_LO + off) = blo;
        }
    };

    // ---- accumulators: warp (wm, wn) owns 64x32 ----
    const int wm = wid >> 2;   // 0..1
    const int wn = wid & 3;    // 0..3
    wmma::fragment<wmma::accumulator, 16, 16, 16, float> acc[4][2];
#pragma unroll
    for (int i = 0; i < 4; ++i)
#pragma unroll
        for (int j = 0; j < 2; ++j) wmma::fill_fragment(acc[i][j], 0.0f);

    auto COMPUTE = [&](char* sb) {
        const __nv_bfloat16* Ahi = (const __nv_bfloat16*)(sb + TCA_HI);
        const __nv_bfloat16* Alo = (const __nv_bfloat16*)(sb + TCA_LO);
        const __nv_bfloat16* Bhi = (const __nv_bfloat16*)(sb + TCB_HI);
        const __nv_bfloat16* Blo = (const __nv_bfloat16*)(sb + TCB_LO);
#pragma unroll
        for (int ks = 0; ks < 2; ++ks) {
            wmma::fragment<wmma::matrix_a, 16, 16, 16, __nv_bfloat16, wmma::row_major> ah[4], al[4];
            wmma::fragment<wmma::matrix_b, 16, 16, 16, __nv_bfloat16, wmma::col_major> bh[2], bl[2];
#pragma unroll
            for (int i = 0; i < 4; ++i) {
                const int ro = (wm * 64 + i * 16) * 40 + ks * 16;
                wmma::load_matrix_sync(ah[i], Ahi + ro, 40);
                wmma::load_matrix_sync(al[i], Alo + ro, 40);
            }
#pragma unroll
            for (int j = 0; j < 2; ++j) {
                const int co = (wn * 32 + j * 16) * 40 + ks * 16;
                wmma::load_matrix_sync(bh[j], Bhi + co, 40);
                wmma::load_matrix_sync(bl[j], Blo + co, 40);
            }
#pragma unroll
            for (int i = 0; i < 4; ++i)
#pragma unroll
                for (int j = 0; j < 2; ++j) {
                    wmma::mma_sync(acc[i][j], ah[i], bh[j], acc[i][j]);
                    wmma::mma_sync(acc[i][j], ah[i], bl[j], acc[i][j]);
                    wmma::mma_sync(acc[i][j], al[i], bh[j], acc[i][j]);
                }
        }
    };

    const int KT = K / 32;
    LOADC(0);
    STOREC(albase);
    __syncthreads();
    for (int kc = 0; kc < KT; ++kc) {
        char* cur = albase + (kc & 1) * TCBUF;
        char* nxt = albase + ((kc & 1) ^ 1) * TCBUF;
        if (kc + 1 < KT) LOADC((kc + 1) * 32);
        COMPUTE(cur);
        if (kc + 1 < KT) STOREC(nxt);
        __syncthreads();
    }

    // ---- epilogue: stage 128x128 fp32 in smem, coalesced scatter ----
    float* stage = (float*)albase;
#pragma unroll
    for (int i = 0; i < 4; ++i)
#pragma unroll
        for (int j = 0; j < 2; ++j)
            wmma::store_matrix_sync(stage + (wm * 64 + i * 16) * 132 + (wn * 32 + j * 16),
                                    acc[i][j], 132, wmma::mem_row_major);
    __syncthreads();
    {
        const int jn = t & 127, rh = t >> 7;
        const int n = ntile * 128 + jn;
        if (n < Ntotal) {
            int b = n / DHW, rem = n - b * DHW;
            size_t obase = ((size_t)b * Cout) * DHW + rem;
#pragma unroll 4
            for (int i = 0; i < 64; ++i) {
                int m = rh * 64 + i;
                int mg = mtile * 128 + m;
                float v = scale * (stage[m * 132 + jn] + bias[mg]);
                out[obase + (size_t)mg * DHW] = fmaxf(v, 0.0f);
            }
        }
    }
}

// ---------------- maxpool + pad (optionally writing packed split words) ----------------
__global__ void pool_pad_kernel(const float* __restrict__ in, float* __restrict__ out,
                                int D, int H, int W,
                                int kd, int kh, int kw, int sd, int sh, int sw,
                                int pd, int ph, int pw,
                                int Do, int Ho, int Wo, int cp, int split)
{
    const int plane = blockIdx.y;
    const int Hp = Ho + 2 * cp, Wp = Wo + 2 * cp, Dp = Do + 2 * cp;
    const int HWp = Hp * Wp;
    const int s = blockIdx.x * blockDim.x + threadIdx.x;
    if (s >= Dp * HWp) return;
    int z = s / HWp;
    int r = s - z * HWp;
    int y = r / Wp;
    int x = r - y * Wp;
    float v = 0.0f;
    int od = z - cp, oh = y - cp, ow = x - cp;
    if (od >= 0 && od < Do && oh >= 0 && oh < Ho && ow >= 0 && ow < Wo) {
        float m = -3.4e38f;
        int id0 = od * sd - pd, ih0 = oh * sh - ph, iw0 = ow * sw - pw;
        const float* base = in + (long)plane * D * H * W;
        for (int a = 0; a < kd; ++a) {
            int id = id0 + a;
            if (id < 0 || id >= D) continue;
            for (int e = 0; e < kh; ++e) {
                int ih = ih0 + e;
                if (ih < 0 || ih >= H) continue;
                for (int f = 0; f < kw; ++f) {
                    int iw = iw0 + f;
                    if (iw < 0 || iw >= W) continue;
                    float q = base[(id * H + ih) * W + iw];
                    m = fmaxf(m, q);
                }
            }
        }
        v = m;
    }
    if (split) ((unsigned*)out)[(long)plane * Dp * HWp + s] = pack_split(v);
    else out[(long)plane * Dp * HWp + s] = v;
}

// ---------------- FC / head ----------------
__global__ void fc_relu_kernel(const float* __restrict__ x, const float* __restrict__ W,
                               const float* __restrict__ b, float* __restrict__ y,
                               int K, int M, int N, float scale)
{
    int idx = blockIdx.x * blockDim.x + threadIdx.x;
    if (idx >= M * N) return;
    int m = idx / N;
    int n = idx - m * N;
    const float4* wr = (const float4*)(W + (size_t)m * K);
    const float4* xr = (const float4*)(x + (size_t)n * K);
    float s = 0.0f;
    int K4 = K >> 2;
#pragma unroll 4
    for (int k = 0; k < K4; ++k) {
        float4 a = wr[k];
        float4 c = xr[k];
        s += a.x * c.x + a.y * c.y + a.z * c.z + a.w * c.w;
    }
    float v = scale * (s + b[m]);
    y[(size_t)n * M + m] = fmaxf(v, 0.0f);
}

__global__ void rownorm_kernel(const float* __restrict__ x, float* __restrict__ nrm, int K)
{
    int row = blockIdx.x;
    float s = 0.0f;
    for (int k = threadIdx.x; k < K; k += 128) {
        float v = x[(size_t)row * K + k];
        s += v * v;
    }
    __shared__ float sm[128];
    sm[threadIdx.x] = s;
    __syncthreads();
    for (int o = 64; o > 0; o >>= 1) {
        if (threadIdx.x < o) sm[threadIdx.x] += sm[threadIdx.x + o];
        __syncthreads();
    }
    if (threadIdx.x == 0) nrm[row] = sqrtf(sm[0]);
}

__global__ void cost_kernel(const float* __restrict__ feat, const float* __restrict__ nrm,
                            float* __restrict__ cost)
{
    int bi = blockIdx.x;
    int j = bi & 3, t2 = bi >> 2;
    int i = t2 & 3, t3 = t2 >> 2;
    int s = t3 % 3, q = t3 / 3;
    int qrow = 12 + q * 4 + i;
    int srow = s * 4 + j;
    const float* a = feat + (size_t)qrow * 4096;
    const float* c = feat + (size_t)srow * 4096;
    float pr = 0.0f;
    for (int k = threadIdx.x; k < 4096; k += 128) pr += a[k] * c[k];
    __shared__ float sm[128];
    sm[threadIdx.x] = pr;
    __syncthreads();
    for (int o = 64; o > 0; o >>= 1) {
        if (threadIdx.x < o) sm[threadIdx.x] += sm[threadIdx.x + o];
        __syncthreads();
    }
    if (threadIdx.x == 0)
        cost[bi] = 1.0f - sm[0] / ((nrm[qrow] + 1e-8f) * (nrm[srow] + 1e-8f));
}

__global__ void sinkhorn_kernel(const float* __restrict__ cost, float* __restrict__ outp)
{
    int t = threadIdx.x;
    if (t >= 9) return;
    float sem[16], Km[16];
    for (int i = 0; i < 4; ++i)
        for (int j = 0; j < 4; ++j) {
            float sc = cost[t * 16 + i * 4 + j];
            float ti = i * 0.25f, tj = j * 0.25f;
            float d2 = (ti - tj) * (ti - tj);
            float pos = expf(-1.0f / (d2 + 1.0f));
            sem[i * 4 + j] = sc;
            Km[i * 4 + j] = expf(-7.0f * (sc + 0.4f * pos));
        }
    float u[4] = {0.25f, 0.25f, 0.25f, 0.25f}, v[4];
    for (int it = 0; it < 100; ++it) {
        for (int j = 0; j < 4; ++j) {
            float s = 1e-9f;
            for (int i = 0; i < 4; ++i) s += Km[i * 4 + j] * u[i];
            v[j] = 0.25f / s;
        }
        for (int i = 0; i < 4; ++i) {
            float s = 1e-9f;
            for (int j = 0; j < 4; ++j) s += Km[i * 4 + j] * v[j];
            u[i] = 0.25f / s;
        }
    }
    for (int j = 0; j < 4; ++j) {
        float s = 1e-9f;
        for (int i = 0; i < 4; ++i) s += Km[i * 4 + j] * u[i];
        v[j] = 0.25f / s;
    }
    float tr = 0.0f;
    for (int i = 0; i < 4; ++i)
        for (int j = 0; j < 4; ++j)
            tr += u[i] * Km[i * 4 + j] * v[j] * sem[i * 4 + j];
    outp[t] = -tr;
}

// ---------------- driver ----------------
static inline int cdiv_i(long a, long b) { return (int)((a + b - 1) / b); }

extern "C" void kernel_launch(void* const* d_in, const int* in_sizes, int n_in,
                              void* d_out, int out_size)
{
    const float* sup  = (const float*)d_in[0];
    const float* qry  = (const float*)d_in[1];
    const float* w1   = (const float*)d_in[2];
    const float* b1   = (const float*)d_in[3];
    const float* w2   = (const float*)d_in[4];
    const float* b2   = (const float*)d_in[5];
    const float* w3a  = (const float*)d_in[6];
    const float* b3a  = (const float*)d_in[7];
    const float* w3b  = (const float*)d_in[8];
    const float* b3b  = (const float*)d_in[9];
    const float* w4a  = (const float*)d_in[10];
    const float* b4a  = (const float*)d_in[11];
    const float* w4b  = (const float*)d_in[12];
    const float* b4b  = (const float*)d_in[13];
    const float* w5a  = (const float*)d_in[14];
    const float* b5a  = (const float*)d_in[15];
    const float* w5b  = (const float*)d_in[16];
    const float* b5b  = (const float*)d_in[17];
    const float* fw6  = (const float*)d_in[18];
    const float* fb6  = (const float*)d_in[19];
    const float* fw7  = (const float*)d_in[20];
    const float* fb7  = (const float*)d_in[21];

    float *pad, *act, *feat, *fc6o, *fc7o, *nrm, *cst, *w1p;
    unsigned* wpk;
    cudaGetSymbolAddress((void**)&pad,  g_pad);
    cudaGetSymbolAddress((void**)&act,  g_act);
    cudaGetSymbolAddress((void**)&feat, g_feat);
    cudaGetSymbolAddress((void**)&fc6o, g_fc6);
    cudaGetSymbolAddress((void**)&fc7o, g_fc7);
    cudaGetSymbolAddress((void**)&nrm,  g_norm);
    cudaGetSymbolAddress((void**)&cst,  g_cost);
    cudaGetSymbolAddress((void**)&w1p,  g_w1);
    cudaGetSymbolAddress((void**)&wpk,  g_wpk);

    const float SC = BN_SCALE_F;
    const int TC_SMEM = 2 * TCBUF + 1024;  // 83 KB
    cudaFuncSetAttribute(conv_tc, cudaFuncAttributeMaxDynamicSharedMemorySize, TC_SMEM);

    // weight packing offsets (words)
    const long O2 = 0, O3A = 221184, O3B = 1105920, O4A = 2875392;
    const long O4B = 6414336, O5A = 13492224, O5B = 20570112;

    rearrange_pad_kernel<<<dim3(cdiv_i(18 * 114 * 114, 256), 72), 256>>>(sup, qry, pad);
    w1prep_kernel<<<cdiv_i(64 * 96, 256), 256>>>(w1, w1p);
    wpack_kernel<<<cdiv_i(221184, 256), 256>>>(w2,  wpk + O2,  221184);
    wpack_kernel<<<cdiv_i(884736, 256), 256>>>(w3a, wpk + O3A, 884736);
    wpack_kernel<<<cdiv_i(1769472, 256), 256>>>(w3b, wpk + O3B, 1769472);
    wpack_kernel<<<cdiv_i(3538944, 256), 256>>>(w4a, wpk + O4A, 3538944);
    wpack_kernel<<<cdiv_i(7077888, 256), 256>>>(w4b, wpk + O4B, 7077888);
    wpack_kernel<<<cdiv_i(7077888, 256), 256>>>(w5a, wpk + O5A, 7077888);
    wpack_kernel<<<cdiv_i(7077888, 256), 256>>>(w5b, wpk + O5B, 7077888);

    // conv1 (SIMT fp32)
    conv_gemm<<<dim3(37632, 1), 256>>>(w1p, pad, act, b1, SC,
                                       3, 16, 112, 112, 81, 96, 64, 4816896);
    // pool1 + pad + split
    pool_pad_kernel<<<dim3(cdiv_i(18 * 58 * 58, 256), 24 * 64), 256>>>(
        act, pad, 16, 112, 112, 1, 2, 2, 1, 2, 2, 0, 0, 0, 16, 56, 56, 1, 1);
    // conv2
    conv_tc<<<dim3(9408, 1), 256, TC_SMEM>>>((unsigned*)(wpk + O2), (unsigned*)pad, act, b2, SC,
                                             64, 16, 56, 56, 1728, 128, 1204224);
    pool_pad_kernel<<<dim3(cdiv_i(10 * 30 * 30, 256), 24 * 128), 256>>>(
        act, pad, 16, 56, 56, 2, 2, 2, 2, 2, 2, 0, 0, 0, 8, 28, 28, 1, 1);
    // conv3a
    conv_tc<<<dim3(1176, 2), 256, TC_SMEM>>>((unsigned*)(wpk + O3A), (unsigned*)pad, act, b3a, 1.0f,
                                             128, 8, 28, 28, 3456, 256, 150528);
    pool_pad_kernel<<<dim3(cdiv_i(10 * 30 * 30, 256), 24 * 256), 256>>>(
        act, pad, 8, 28, 28, 1, 1, 1, 1, 1, 1, 0, 0, 0, 8, 28, 28, 1, 1);
    // conv3b
    conv_tc<<<dim3(1176, 2), 256, TC_SMEM>>>((unsigned*)(wpk + O3B), (unsigned*)pad, act, b3b, SC,
                                             256, 8, 28, 28, 6912, 256, 150528);
    pool_pad_kernel<<<dim3(cdiv_i(6 * 16 * 16, 256), 24 * 256), 256>>>(
        act, pad, 8, 28, 28, 2, 2, 2, 2, 2, 2, 0, 0, 0, 4, 14, 14, 1, 1);
    // conv4a
    conv_tc<<<dim3(147, 4), 256, TC_SMEM>>>((unsigned*)(wpk + O4A), (unsigned*)pad, act, b4a, 1.0f,
                                            256, 4, 14, 14, 6912, 512, 18816);
    pool_pad_kernel<<<dim3(cdiv_i(6 * 16 * 16, 256), 24 * 512), 256>>>(
        act, pad, 4, 14, 14, 1, 1, 1, 1, 1, 1, 0, 0, 0, 4, 14, 14, 1, 1);
    // conv4b
    conv_tc<<<dim3(147, 4), 256, TC_SMEM>>>((unsigned*)(wpk + O4B), (unsigned*)pad, act, b4b, SC,
                                            512, 4, 14, 14, 13824, 512, 18816);
    pool_pad_kernel<<<dim3(cdiv_i(4 * 9 * 9, 256), 24 * 512), 256>>>(
        act, pad, 4, 14, 14, 2, 2, 2, 2, 2, 2, 0, 0, 0, 2, 7, 7, 1, 1);
    // conv5a
    conv_tc<<<dim3(19, 4), 256, TC_SMEM>>>((unsigned*)(wpk + O5A), (unsigned*)pad, act, b5a, 1.0f,
                                           512, 2, 7, 7, 13824, 512, 2352);
    pool_pad_kernel<<<dim3(cdiv_i(4 * 9 * 9, 256), 24 * 512), 256>>>(
        act, pad, 2, 7, 7, 1, 1, 1, 1, 1, 1, 0, 0, 0, 2, 7, 7, 1, 1);
    // conv5b
    conv_tc<<<dim3(19, 4), 256, TC_SMEM>>>((unsigned*)(wpk + O5B), (unsigned*)pad, act, b5b, SC,
                                           512, 2, 7, 7, 13824, 512, 2352);
    // pool5 -> features (fp32)
    pool_pad_kernel<<<dim3(1, 24 * 512), 256>>>(
        act, feat, 2, 7, 7, 2, 2, 2, 2, 2, 2, 0, 1, 1, 1, 4, 4, 0, 0);
    // fc6, fc7
    fc_relu_kernel<<<cdiv_i(4096 * 24, 256), 256>>>(feat, fw6, fb6, fc6o, 8192, 4096, 24, SC);
    fc_relu_kernel<<<cdiv_i(4096 * 24, 256), 256>>>(fc6o, fw7, fb7, fc7o, 4096, 4096, 24, SC);
    // head
    rownorm_kernel<<<24, 128>>>(fc7o, nrm, 4096);
    cost_kernel<<<144, 128>>>(fc7o, nrm, cst);
    sinkhorn_kernel<<<1, 32>>>(cst, (float*)d_out);
}

// round 10
// speedup vs baseline: 1.8060x; 1.1879x over previous
#include <cuda_runtime.h>
#include <cuda_bf16.h>
#include <mma.h>
#include <math.h>
#include <stdint.h>

using namespace nvcuda;

#define BN_SCALE_F 0.9999950000374996f

// ---------------- static scratch ----------------
__device__ float g_pad[93007872];
__device__ float g_act[308281344];
__device__ float g_feat[24 * 8192];
__device__ float g_fc6[24 * 4096];
__device__ float g_fc7[24 * 4096];
__device__ float g_norm[24];
__device__ float g_cost[144];
__device__ float g_w1[64 * 96];
__device__ unsigned g_wpk[27648000];   // packed split weights conv2..conv5b

// ---------------- helpers ----------------
__device__ __forceinline__ unsigned pack_split(float v) {
    float hf = __uint_as_float(__float_as_uint(v) & 0xFFFF0000u);  // truncate-to-bf16 hi
    unsigned hi = __float_as_uint(hf) >> 16;
    float r = v - hf;
    unsigned lo = __float_as_uint(r) >> 16;                        // truncated lo
    return hi | (lo << 16);
}
__device__ __forceinline__ void ffma2(unsigned long long& d, unsigned long long a, unsigned long long b) {
    asm("fma.rn.f32x2 %0, %1, %2, %0;" : "+l"(d) : "l"(a), "l"(b));
}
__device__ __forceinline__ unsigned long long splat2(float x) {
    unsigned long long r;
    asm("mov.b64 %0, {%1, %1};" : "=l"(r) : "f"(x));
    return r;
}
__device__ __forceinline__ void unpack2(unsigned long long p, float& lo, float& hi) {
    asm("mov.b64 {%0, %1}, %2;" : "=f"(lo), "=f"(hi) : "l"(p));
}

// ---------------- input rearrange + pad (fp32) ----------------
__global__ void rearrange_pad_kernel(const float* __restrict__ sup, const float* __restrict__ qry,
                                     float* __restrict__ out)
{
    const int plane = blockIdx.y;
    const int clip = plane / 3;
    const int c = plane - clip * 3;
    const int s = blockIdx.x * blockDim.x + threadIdx.x;
    const int HWp = 114 * 114;
    if (s >= 18 * HWp) return;
    int dz = s / HWp;
    int r = s - dz * HWp;
    int hy = r / 114;
    int wx = r - hy * 114;
    float val = 0.0f;
    if (dz >= 1 && dz <= 16 && hy >= 1 && hy <= 112 && wx >= 1 && wx <= 112) {
        int tt = dz - 1, h = hy - 1, w = wx - 1;
        const float* src = (clip < 12) ? sup : qry;
        int cc = (clip < 12) ? clip : clip - 12;
        long addr = ((((long)cc * 16 + tt) * 3 + c) * 112 + h) * 112 + w;
        val = src[addr];
    }
    out[(long)plane * 18 * HWp + s] = val;
}

__global__ void w1prep_kernel(const float* __restrict__ w, float* __restrict__ out)
{
    int idx = blockIdx.x * blockDim.x + threadIdx.x;
    if (idx >= 64 * 96) return;
    int m = idx / 96, k = idx - m * 96;
    out[idx] = (k < 81) ? w[m * 81 + k] : 0.0f;
}

__global__ void wpack_kernel(const float* __restrict__ w, unsigned* __restrict__ out, int n)
{
    int i = blockIdx.x * blockDim.x + threadIdx.x;
    if (i < n) out[i] = pack_split(w[i]);
}

// ---------------- conv1: SIMT implicit GEMM (fp32, f32x2 FMA) ----------------
__global__ __launch_bounds__(256, 2)
void conv_gemm(const float* __restrict__ A, const float* __restrict__ inp,
               float* __restrict__ out, const float* __restrict__ bias, float scale,
               int Cin, int D, int H, int W, int Ktrue, int Kpad, int Cout, int Ntotal)
{
    constexpr int BM = 64, BNt = 128, BK = 16, MR = 4;
    const int Hp = H + 2, Wp = W + 2;
    const int HWp = Hp * Wp;
    const int chanStride = (D + 2) * HWp;
    const int HW = H * W;
    const int DHW = D * HW;

    __shared__ float sA[2][BK][BM];
    __shared__ float sB[2][BK][BNt];

    const int tid = threadIdx.x;
    const int tx = tid & 15;
    const int ty = tid >> 4;
    const int ntile = blockIdx.x;
    const int mtile = blockIdx.y;

    const int krow = ty;
    const int n0 = tx * 8;
    int nbase[8];
#pragma unroll
    for (int j = 0; j < 8; ++j) {
        int n = ntile * BNt + n0 + j;
        if (n >= Ntotal) n = Ntotal - 1;
        int b = n / DHW;
        int rem = n - b * DHW;
        int d = rem / HW;
        int r2 = rem - d * HW;
        int h = r2 / W;
        int w = r2 - h * W;
        nbase[j] = b * Cin * chanStride + d * HWp + h * Wp + w;
    }

    const int am = tid & (BM - 1);
    const int akg = tid / BM;
    const float* Aptr = A + (size_t)(mtile * BM + am) * Kpad;

    float4 stA0;
    float stB[8];
    int koff = 0;

    auto LOADK = [&](int k0_) {
        stA0 = *(const float4*)(Aptr + k0_ + akg * 4);
        int kg_ = k0_ + krow;
        int ke_ = (kg_ < Ktrue) ? kg_ : 0;
        int ci_ = ke_ / 27;
        int r_ = ke_ - ci_ * 27;
        int kd_ = r_ / 9; r_ -= kd_ * 9;
        int kh_ = r_ / 3;
        int kw_ = r_ - kh_ * 3;
        koff = ci_ * chanStride + kd_ * HWp + kh_ * Wp + kw_;
#pragma unroll
        for (int j = 0; j < 8; ++j) stB[j] = __ldg(inp + nbase[j] + koff);
    };
    auto STORETILE = [&](int bf_) {
        int kb_ = akg * 4;
        sA[bf_][kb_ + 0][am] = stA0.x;
        sA[bf_][kb_ + 1][am] = stA0.y;
        sA[bf_][kb_ + 2][am] = stA0.z;
        sA[bf_][kb_ + 3][am] = stA0.w;
        *(float4*)&sB[bf_][krow][n0]     = make_float4(stB[0], stB[1], stB[2], stB[3]);
        *(float4*)&sB[bf_][krow][n0 + 4] = make_float4(stB[4], stB[5], stB[6], stB[7]);
    };

    unsigned long long acc2[MR][4];
#pragma unroll
    for (int i = 0; i < MR; ++i)
#pragma unroll
        for (int jp = 0; jp < 4; ++jp) acc2[i][jp] = 0ULL;

    const int KT = Kpad / BK;
    LOADK(0);
    STORETILE(0);
    __syncthreads();

    for (int kt = 0; kt < KT; ++kt) {
        int buf = kt & 1;
        if (kt + 1 < KT) LOADK((kt + 1) * BK);
#pragma unroll
        for (int kk = 0; kk < BK; ++kk) {
            ulonglong2 b0 = *(const ulonglong2*)&sB[buf][kk][tx * 4];
            ulonglong2 b1 = *(const ulonglong2*)&sB[buf][kk][64 + tx * 4];
            unsigned long long bp[4] = {b0.x, b0.y, b1.x, b1.y};
            float4 a0 = *(const float4*)&sA[buf][kk][ty * 4];
            float af[MR] = {a0.x, a0.y, a0.z, a0.w};
#pragma unroll
            for (int i = 0; i < MR; ++i) {
                unsigned long long a2 = splat2(af[i]);
                ffma2(acc2[i][0], a2, bp[0]);
                ffma2(acc2[i][1], a2, bp[1]);
                ffma2(acc2[i][2], a2, bp[2]);
                ffma2(acc2[i][3], a2, bp[3]);
            }
        }
        if (kt + 1 < KT) STORETILE(buf ^ 1);
        __syncthreads();
    }

#pragma unroll
    for (int jp = 0; jp < 4; ++jp) {
        int colbase = (jp < 2) ? (tx * 4 + jp * 2) : (64 + tx * 4 + (jp - 2) * 2);
#pragma unroll
        for (int half = 0; half < 2; ++half) {
            int n = ntile * BNt + colbase + half;
            if (n >= Ntotal) continue;
            int b = n / DHW;
            int rem = n - b * DHW;
            size_t obase = ((size_t)b * Cout) * DHW + rem;
#pragma unroll
            for (int i = 0; i < MR; ++i) {
                int m = mtile * BM + ty * 4 + i;
                float lo, hi;
                unpack2(acc2[i][jp], lo, hi);
                float v = scale * (((half == 0) ? lo : hi) + bias[m]);
                out[obase + (size_t)m * DHW] = fmaxf(v, 0.0f);
            }
        }
    }
}

// ---------------- wmma split-bf16 conv (conv2..conv5b) ----------------
// GEMM: M=Cout (128/tile), N=spatial (128/tile), K chunks of 32.
// smem per buffer: A_hi/A_lo [128][40] bf16, B_hi/B_lo [128][40] bf16.
#define TCA_HI 0
#define TCA_LO 10240
#define TCB_HI 20480
#define TCB_LO 30720
#define TCBUF  40960

__global__ __launch_bounds__(256)
void conv_tc(const unsigned* __restrict__ wpk, const unsigned* __restrict__ inp,
             float* __restrict__ out, const float* __restrict__ bias, float scale,
             int Cin, int D, int H, int W, int K, int Cout, int Ntotal)
{
    extern __shared__ char dsm[];
    char* albase = (char*)(((uintptr_t)dsm + 1023) & ~(uintptr_t)1023);

    const int Hp = H + 2, Wp = W + 2;
    const int HWp = Hp * Wp;
    const int chanStride = (D + 2) * HWp;
    const int HW = H * W;
    const int DHW = D * HW;

    const int t = threadIdx.x;
    const int wid = t >> 5;
    const int ntile = blockIdx.x;
    const int mtile = blockIdx.y;

    // ---- A gather mapping (coalesced along K): p = kpair, rbase = row ----
    const int p = t & 15;
    const int rbase = t >> 4;
    const unsigned* Awp = wpk + (size_t)(mtile * 128 + rbase) * K + 2 * p;

    // ---- B gather mapping (coalesced along N): nl = lane->n, kb = warp->4 k ----
    const int nl = t & 31;
    const int kb = (t >> 5) << 2;   // 0,4,...,28
    int nbB[4];
#pragma unroll
    for (int i = 0; i < 4; ++i) {
        int n = ntile * 128 + i * 32 + nl;
        if (n >= Ntotal) n = Ntotal - 1;
        int b = n / DHW;
        int rem = n - b * DHW;
        int d = rem / HW;
        int r2 = rem - d * HW;
        int h = r2 / W;
        int w = r2 - h * W;
        nbB[i] = b * Cin * chanStride + d * HWp + h * Wp + w;
    }

    uint2 aw[8];
    uint32_t bw[4][4];

    auto LOADC = [&](int k0) {
#pragma unroll
        for (int i = 0; i < 8; ++i)
            aw[i] = *(const uint2*)(Awp + (size_t)(16 * i) * K + k0);
        int ko[4];
#pragma unroll
        for (int j = 0; j < 4; ++j) {
            int k = k0 + kb + j;
            int ci = k / 27, r_ = k - ci * 27;
            int kd = r_ / 9; r_ -= kd * 9;
            int kh = r_ / 3, kw = r_ - kh * 3;
            ko[j] = ci * chanStride + kd * HWp + kh * Wp + kw;
        }
#pragma unroll
        for (int i = 0; i < 4; ++i)
#pragma unroll
            for (int j = 0; j < 4; ++j)
                bw[i][j] = __ldg(inp + nbB[i] + ko[j]);
    };

    auto STOREC = [&](char* sb) {
#pragma unroll
        for (int i = 0; i < 8; ++i) {
            int off = (rbase + 16 * i) * 80 + p * 4;
            uint32_t ahi, alo;
            asm("prmt.b32 %0, %1, %2, 0x5410;" : "=r"(ahi) : "r"(aw[i].x), "r"(aw[i].y));
            asm("prmt.b32 %0, %1, %2, 0x7632;" : "=r"(alo) : "r"(aw[i].x), "r"(aw[i].y));
            *(uint32_t*)(sb + TCA_HI + off) = ahi;
            *(uint32_t*)(sb + TCA_LO + off) = alo;
        }
#pragma unroll
        for (int i = 0; i < 4; ++i)
#pragma unroll
            for (int jp = 0; jp < 2; ++jp) {
                int j = jp * 2;
                uint32_t bhi, blo;
                asm("prmt.b32 %0, %1, %2, 0x5410;" : "=r"(bhi) : "r"(bw[i][j]), "r"(bw[i][j + 1]));
                asm("prmt.b32 %0, %1, %2, 0x7632;" : "=r"(blo) : "r"(bw[i][j]), "r"(bw[i][j + 1]));
                int off = (i * 32 + nl) * 80 + (kb + j) * 2;
                *(uint32_t*)(sb + TCB_HI + off) = bhi;
                *(uint32_t*)(sb + TCB_LO + off) = blo;
            }
    };

    // ---- accumulators: warp (wm, wn) owns 64x32 ----
    const int wm = wid >> 2;   // 0..1
    const int wn = wid & 3;    // 0..3
    wmma::fragment<wmma::accumulator, 16, 16, 16, float> acc[4][2];
#pragma unroll
    for (int i = 0; i < 4; ++i)
#pragma unroll
        for (int j = 0; j < 2; ++j) wmma::fill_fragment(acc[i][j], 0.0f);

    auto COMPUTE = [&](char* sb) {
        const __nv_bfloat16* Ahi = (const __nv_bfloat16*)(sb + TCA_HI);
        const __nv_bfloat16* Alo = (const __nv_bfloat16*)(sb + TCA_LO);
        const __nv_bfloat16* Bhi = (const __nv_bfloat16*)(sb + TCB_HI);
        const __nv_bfloat16* Blo = (const __nv_bfloat16*)(sb + TCB_LO);
#pragma unroll
        for (int ks = 0; ks < 2; ++ks) {
            wmma::fragment<wmma::matrix_a, 16, 16, 16, __nv_bfloat16, wmma::row_major> ah[4], al[4];
            wmma::fragment<wmma::matrix_b, 16, 16, 16, __nv_bfloat16, wmma::col_major> bh[2], bl[2];
#pragma unroll
            for (int i = 0; i < 4; ++i) {
                const int ro = (wm * 64 + i * 16) * 40 + ks * 16;
                wmma::load_matrix_sync(ah[i], Ahi + ro, 40);
                wmma::load_matrix_sync(al[i], Alo + ro, 40);
            }
#pragma unroll
            for (int j = 0; j < 2; ++j) {
                const int co = (wn * 32 + j * 16) * 40 + ks * 16;
                wmma::load_matrix_sync(bh[j], Bhi + co, 40);
                wmma::load_matrix_sync(bl[j], Blo + co, 40);
            }
#pragma unroll
            for (int i = 0; i < 4; ++i)
#pragma unroll
                for (int j = 0; j < 2; ++j) {
                    wmma::mma_sync(acc[i][j], ah[i], bh[j], acc[i][j]);
                    wmma::mma_sync(acc[i][j], ah[i], bl[j], acc[i][j]);
                    wmma::mma_sync(acc[i][j], al[i], bh[j], acc[i][j]);
                }
        }
    };

    const int KT = K / 32;
    LOADC(0);
    STOREC(albase);
    __syncthreads();
    for (int kc = 0; kc < KT; ++kc) {
        char* cur = albase + (kc & 1) * TCBUF;
        char* nxt = albase + ((kc & 1) ^ 1) * TCBUF;
        if (kc + 1 < KT) LOADC((kc + 1) * 32);
        COMPUTE(cur);
        if (kc + 1 < KT) STOREC(nxt);
        __syncthreads();
    }

    // ---- epilogue: stage 128x128 fp32 in smem, coalesced scatter ----
    float* stage = (float*)albase;
#pragma unroll
    for (int i = 0; i < 4; ++i)
#pragma unroll
        for (int j = 0; j < 2; ++j)
            wmma::store_matrix_sync(stage + (wm * 64 + i * 16) * 132 + (wn * 32 + j * 16),
                                    acc[i][j], 132, wmma::mem_row_major);
    __syncthreads();
    {
        const int jn = t & 127, rh = t >> 7;
        const int n = ntile * 128 + jn;
        if (n < Ntotal) {
            int b = n / DHW, rem = n - b * DHW;
            size_t obase = ((size_t)b * Cout) * DHW + rem;
#pragma unroll 4
            for (int i = 0; i < 64; ++i) {
                int m = rh * 64 + i;
                int mg = mtile * 128 + m;
                float v = scale * (stage[m * 132 + jn] + bias[mg]);
                out[obase + (size_t)mg * DHW] = fmaxf(v, 0.0f);
            }
        }
    }
}

// ---------------- maxpool + pad (optionally writing packed split words) ----------------
__global__ void pool_pad_kernel(const float* __restrict__ in, float* __restrict__ out,
                                int D, int H, int W,
                                int kd, int kh, int kw, int sd, int sh, int sw,
                                int pd, int ph, int pw,
                                int Do, int Ho, int Wo, int cp, int split)
{
    const int plane = blockIdx.y;
    const int Hp = Ho + 2 * cp, Wp = Wo + 2 * cp, Dp = Do + 2 * cp;
    const int HWp = Hp * Wp;
    const int s = blockIdx.x * blockDim.x + threadIdx.x;
    if (s >= Dp * HWp) return;
    int z = s / HWp;
    int r = s - z * HWp;
    int y = r / Wp;
    int x = r - y * Wp;
    float v = 0.0f;
    int od = z - cp, oh = y - cp, ow = x - cp;
    if (od >= 0 && od < Do && oh >= 0 && oh < Ho && ow >= 0 && ow < Wo) {
        float m = -3.4e38f;
        int id0 = od * sd - pd, ih0 = oh * sh - ph, iw0 = ow * sw - pw;
        const float* base = in + (long)plane * D * H * W;
        for (int a = 0; a < kd; ++a) {
            int id = id0 + a;
            if (id < 0 || id >= D) continue;
            for (int e = 0; e < kh; ++e) {
                int ih = ih0 + e;
                if (ih < 0 || ih >= H) continue;
                for (int f = 0; f < kw; ++f) {
                    int iw = iw0 + f;
                    if (iw < 0 || iw >= W) continue;
                    float q = base[(id * H + ih) * W + iw];
                    m = fmaxf(m, q);
                }
            }
        }
        v = m;
    }
    if (split) ((unsigned*)out)[(long)plane * Dp * HWp + s] = pack_split(v);
    else out[(long)plane * Dp * HWp + s] = v;
}

// ---------------- tiled FC: warp-per-row, x chunk in smem ----------------
// y[n][m] = relu(scale * (x[n].W[m] + b[m]));  N = 24 fixed
__global__ __launch_bounds__(256)
void fc_tile_kernel(const float* __restrict__ x, const float* __restrict__ W,
                    const float* __restrict__ b, float* __restrict__ y,
                    int K, int M, float scale)
{
    __shared__ float xs[24][260];
    const int warp = threadIdx.x >> 5, lane = threadIdx.x & 31;
    const int m = blockIdx.x * 8 + warp;
    float acc[24];
#pragma unroll
    for (int n = 0; n < 24; ++n) acc[n] = 0.0f;

    const float* wr = W + (size_t)m * K;
    for (int k0 = 0; k0 < K; k0 += 256) {
        __syncthreads();
        for (int i = threadIdx.x; i < 24 * 64; i += 256) {
            int n = i / 64, kq = i - n * 64;
            *(float4*)&xs[n][kq * 4] = *(const float4*)(x + (size_t)n * K + k0 + kq * 4);
        }
        __syncthreads();
#pragma unroll 2
        for (int kq = lane; kq < 64; kq += 32) {
            float4 w4 = *(const float4*)(wr + k0 + kq * 4);
#pragma unroll
            for (int n = 0; n < 24; ++n) {
                float4 x4 = *(const float4*)&xs[n][kq * 4];
                acc[n] += w4.x * x4.x + w4.y * x4.y + w4.z * x4.z + w4.w * x4.w;
            }
        }
    }
#pragma unroll
    for (int n = 0; n < 24; ++n) {
#pragma unroll
        for (int o = 16; o > 0; o >>= 1)
            acc[n] += __shfl_xor_sync(0xFFFFFFFFu, acc[n], o);
    }
    if (lane == 0) {
#pragma unroll
        for (int n = 0; n < 24; ++n) {
            float v = scale * (acc[n] + b[m]);
            y[(size_t)n * M + m] = fmaxf(v, 0.0f);
        }
    }
}

__global__ void rownorm_kernel(const float* __restrict__ x, float* __restrict__ nrm, int K)
{
    int row = blockIdx.x;
    float s = 0.0f;
    for (int k = threadIdx.x; k < K; k += 128) {
        float v = x[(size_t)row * K + k];
        s += v * v;
    }
    __shared__ float sm[128];
    sm[threadIdx.x] = s;
    __syncthreads();
    for (int o = 64; o > 0; o >>= 1) {
        if (threadIdx.x < o) sm[threadIdx.x] += sm[threadIdx.x + o];
        __syncthreads();
    }
    if (threadIdx.x == 0) nrm[row] = sqrtf(sm[0]);
}

__global__ void cost_kernel(const float* __restrict__ feat, const float* __restrict__ nrm,
                            float* __restrict__ cost)
{
    int bi = blockIdx.x;
    int j = bi & 3, t2 = bi >> 2;
    int i = t2 & 3, t3 = t2 >> 2;
    int s = t3 % 3, q = t3 / 3;
    int qrow = 12 + q * 4 + i;
    int srow = s * 4 + j;
    const float* a = feat + (size_t)qrow * 4096;
    const float* c = feat + (size_t)srow * 4096;
    float pr = 0.0f;
    for (int k = threadIdx.x; k < 4096; k += 128) pr += a[k] * c[k];
    __shared__ float sm[128];
    sm[threadIdx.x] = pr;
    __syncthreads();
    for (int o = 64; o > 0; o >>= 1) {
        if (threadIdx.x < o) sm[threadIdx.x] += sm[threadIdx.x + o];
        __syncthreads();
    }
    if (threadIdx.x == 0)
        cost[bi] = 1.0f - sm[0] / ((nrm[qrow] + 1e-8f) * (nrm[srow] + 1e-8f));
}

__global__ void sinkhorn_kernel(const float* __restrict__ cost, float* __restrict__ outp)
{
    int t = threadIdx.x;
    if (t >= 9) return;
    float sem[16], Km[16];
    for (int i = 0; i < 4; ++i)
        for (int j = 0; j < 4; ++j) {
            float sc = cost[t * 16 + i * 4 + j];
            float ti = i * 0.25f, tj = j * 0.25f;
            float d2 = (ti - tj) * (ti - tj);
            float pos = expf(-1.0f / (d2 + 1.0f));
            sem[i * 4 + j] = sc;
            Km[i * 4 + j] = expf(-7.0f * (sc + 0.4f * pos));
        }
    float u[4] = {0.25f, 0.25f, 0.25f, 0.25f}, v[4];
    for (int it = 0; it < 100; ++it) {
        for (int j = 0; j < 4; ++j) {
            float s = 1e-9f;
            for (int i = 0; i < 4; ++i) s += Km[i * 4 + j] * u[i];
            v[j] = 0.25f / s;
        }
        for (int i = 0; i < 4; ++i) {
            float s = 1e-9f;
            for (int j = 0; j < 4; ++j) s += Km[i * 4 + j] * v[j];
            u[i] = 0.25f / s;
        }
    }
    for (int j = 0; j < 4; ++j) {
        float s = 1e-9f;
        for (int i = 0; i < 4; ++i) s += Km[i * 4 + j] * u[i];
        v[j] = 0.25f / s;
    }
    float tr = 0.0f;
    for (int i = 0; i < 4; ++i)
        for (int j = 0; j < 4; ++j)
            tr += u[i] * Km[i * 4 + j] * v[j] * sem[i * 4 + j];
    outp[t] = -tr;
}

// ---------------- driver ----------------
static inline int cdiv_i(long a, long b) { return (int)((a + b - 1) / b); }

extern "C" void kernel_launch(void* const* d_in, const int* in_sizes, int n_in,
                              void* d_out, int out_size)
{
    const float* sup  = (const float*)d_in[0];
    const float* qry  = (const float*)d_in[1];
    const float* w1   = (const float*)d_in[2];
    const float* b1   = (const float*)d_in[3];
    const float* w2   = (const float*)d_in[4];
    const float* b2   = (const float*)d_in[5];
    const float* w3a  = (const float*)d_in[6];
    const float* b3a  = (const float*)d_in[7];
    const float* w3b  = (const float*)d_in[8];
    const float* b3b  = (const float*)d_in[9];
    const float* w4a  = (const float*)d_in[10];
    const float* b4a  = (const float*)d_in[11];
    const float* w4b  = (const float*)d_in[12];
    const float* b4b  = (const float*)d_in[13];
    const float* w5a  = (const float*)d_in[14];
    const float* b5a  = (const float*)d_in[15];
    const float* w5b  = (const float*)d_in[16];
    const float* b5b  = (const float*)d_in[17];
    const float* fw6  = (const float*)d_in[18];
    const float* fb6  = (const float*)d_in[19];
    const float* fw7  = (const float*)d_in[20];
    const float* fb7  = (const float*)d_in[21];

    float *pad, *act, *feat, *fc6o, *fc7o, *nrm, *cst, *w1p;
    unsigned* wpk;
    cudaGetSymbolAddress((void**)&pad,  g_pad);
    cudaGetSymbolAddress((void**)&act,  g_act);
    cudaGetSymbolAddress((void**)&feat, g_feat);
    cudaGetSymbolAddress((void**)&fc6o, g_fc6);
    cudaGetSymbolAddress((void**)&fc7o, g_fc7);
    cudaGetSymbolAddress((void**)&nrm,  g_norm);
    cudaGetSymbolAddress((void**)&cst,  g_cost);
    cudaGetSymbolAddress((void**)&w1p,  g_w1);
    cudaGetSymbolAddress((void**)&wpk,  g_wpk);

    const float SC = BN_SCALE_F;
    const int TC_SMEM = 2 * TCBUF + 1024;  // 83 KB
    cudaFuncSetAttribute(conv_tc, cudaFuncAttributeMaxDynamicSharedMemorySize, TC_SMEM);

    // weight packing offsets (words)
    const long O2 = 0, O3A = 221184, O3B = 1105920, O4A = 2875392;
    const long O4B = 6414336, O5A = 13492224, O5B = 20570112;

    rearrange_pad_kernel<<<dim3(cdiv_i(18 * 114 * 114, 256), 72), 256>>>(sup, qry, pad);
    w1prep_kernel<<<cdiv_i(64 * 96, 256), 256>>>(w1, w1p);
    wpack_kernel<<<cdiv_i(221184, 256), 256>>>(w2,  wpk + O2,  221184);
    wpack_kernel<<<cdiv_i(884736, 256), 256>>>(w3a, wpk + O3A, 884736);
    wpack_kernel<<<cdiv_i(1769472, 256), 256>>>(w3b, wpk + O3B, 1769472);
    wpack_kernel<<<cdiv_i(3538944, 256), 256>>>(w4a, wpk + O4A, 3538944);
    wpack_kernel<<<cdiv_i(7077888, 256), 256>>>(w4b, wpk + O4B, 7077888);
    wpack_kernel<<<cdiv_i(7077888, 256), 256>>>(w5a, wpk + O5A, 7077888);
    wpack_kernel<<<cdiv_i(7077888, 256), 256>>>(w5b, wpk + O5B, 7077888);

    // conv1 (SIMT fp32)
    conv_gemm<<<dim3(37632, 1), 256>>>(w1p, pad, act, b1, SC,
                                       3, 16, 112, 112, 81, 96, 64, 4816896);
    // pool1 + pad + split
    pool_pad_kernel<<<dim3(cdiv_i(18 * 58 * 58, 256), 24 * 64), 256>>>(
        act, pad, 16, 112, 112, 1, 2, 2, 1, 2, 2, 0, 0, 0, 16, 56, 56, 1, 1);
    // conv2
    conv_tc<<<dim3(9408, 1), 256, TC_SMEM>>>((unsigned*)(wpk + O2), (unsigned*)pad, act, b2, SC,
                                             64, 16, 56, 56, 1728, 128, 1204224);
    pool_pad_kernel<<<dim3(cdiv_i(10 * 30 * 30, 256), 24 * 128), 256>>>(
        act, pad, 16, 56, 56, 2, 2, 2, 2, 2, 2, 0, 0, 0, 8, 28, 28, 1, 1);
    // conv3a
    conv_tc<<<dim3(1176, 2), 256, TC_SMEM>>>((unsigned*)(wpk + O3A), (unsigned*)pad, act, b3a, 1.0f,
                                             128, 8, 28, 28, 3456, 256, 150528);
    pool_pad_kernel<<<dim3(cdiv_i(10 * 30 * 30, 256), 24 * 256), 256>>>(
        act, pad, 8, 28, 28, 1, 1, 1, 1, 1, 1, 0, 0, 0, 8, 28, 28, 1, 1);
    // conv3b
    conv_tc<<<dim3(1176, 2), 256, TC_SMEM>>>((unsigned*)(wpk + O3B), (unsigned*)pad, act, b3b, SC,
                                             256, 8, 28, 28, 6912, 256, 150528);
    pool_pad_kernel<<<dim3(cdiv_i(6 * 16 * 16, 256), 24 * 256), 256>>>(
        act, pad, 8, 28, 28, 2, 2, 2, 2, 2, 2, 0, 0, 0, 4, 14, 14, 1, 1);
    // conv4a
    conv_tc<<<dim3(147, 4), 256, TC_SMEM>>>((unsigned*)(wpk + O4A), (unsigned*)pad, act, b4a, 1.0f,
                                            256, 4, 14, 14, 6912, 512, 18816);
    pool_pad_kernel<<<dim3(cdiv_i(6 * 16 * 16, 256), 24 * 512), 256>>>(
        act, pad, 4, 14, 14, 1, 1, 1, 1, 1, 1, 0, 0, 0, 4, 14, 14, 1, 1);
    // conv4b
    conv_tc<<<dim3(147, 4), 256, TC_SMEM>>>((unsigned*)(wpk + O4B), (unsigned*)pad, act, b4b, SC,
                                            512, 4, 14, 14, 13824, 512, 18816);
    pool_pad_kernel<<<dim3(cdiv_i(4 * 9 * 9, 256), 24 * 512), 256>>>(
        act, pad, 4, 14, 14, 2, 2, 2, 2, 2, 2, 0, 0, 0, 2, 7, 7, 1, 1);
    // conv5a
    conv_tc<<<dim3(19, 4), 256, TC_SMEM>>>((unsigned*)(wpk + O5A), (unsigned*)pad, act, b5a, 1.0f,
                                           512, 2, 7, 7, 13824, 512, 2352);
    pool_pad_kernel<<<dim3(cdiv_i(4 * 9 * 9, 256), 24 * 512), 256>>>(
        act, pad, 2, 7, 7, 1, 1, 1, 1, 1, 1, 0, 0, 0, 2, 7, 7, 1, 1);
    // conv5b
    conv_tc<<<dim3(19, 4), 256, TC_SMEM>>>((unsigned*)(wpk + O5B), (unsigned*)pad, act, b5b, SC,
                                           512, 2, 7, 7, 13824, 512, 2352);
    // pool5 -> features (fp32)
    pool_pad_kernel<<<dim3(1, 24 * 512), 256>>>(
        act, feat, 2, 7, 7, 2, 2, 2, 2, 2, 2, 0, 1, 1, 1, 4, 4, 0, 0);
    // fc6, fc7 (tiled)
    fc_tile_kernel<<<512, 256>>>(feat, fw6, fb6, fc6o, 8192, 4096, SC);
    fc_tile_kernel<<<512, 256>>>(fc6o, fw7, fb7, fc7o, 4096, 4096, SC);
    // head
    rownorm_kernel<<<24, 128>>>(fc7o, nrm, 4096);
    cost_kernel<<<144, 128>>>(fc7o, nrm, cst);
    sinkhorn_kernel<<<1, 32>>>(cst, (float*)d_out);
}

// round 11
// speedup vs baseline: 1.9873x; 1.1004x over previous
#include <cuda_runtime.h>
#include <cuda_bf16.h>
#include <mma.h>
#include <math.h>
#include <stdint.h>

using namespace nvcuda;

#define BN_SCALE_F 0.9999950000374996f

// ---------------- static scratch ----------------
__device__ float g_pad[93007872];
__device__ float g_act[308281344];
__device__ float g_feat[24 * 8192];
__device__ float g_fc6[24 * 4096];
__device__ float g_fc7[24 * 4096];
__device__ float g_norm[24];
__device__ float g_cost[144];
__device__ float g_w1[64 * 96];
__device__ unsigned g_wpk[27648000];   // packed split weights conv2..conv5b

// ---------------- helpers ----------------
__device__ __forceinline__ unsigned pack_split(float v) {
    float hf = __uint_as_float(__float_as_uint(v) & 0xFFFF0000u);  // truncate-to-bf16 hi
    unsigned hi = __float_as_uint(hf) >> 16;
    float r = v - hf;
    unsigned lo = __float_as_uint(r) >> 16;                        // truncated lo
    return hi | (lo << 16);
}
__device__ __forceinline__ void ffma2(unsigned long long& d, unsigned long long a, unsigned long long b) {
    asm("fma.rn.f32x2 %0, %1, %2, %0;" : "+l"(d) : "l"(a), "l"(b));
}
__device__ __forceinline__ unsigned long long splat2(float x) {
    unsigned long long r;
    asm("mov.b64 %0, {%1, %1};" : "=l"(r) : "f"(x));
    return r;
}
__device__ __forceinline__ void unpack2(unsigned long long p, float& lo, float& hi) {
    asm("mov.b64 {%0, %1}, %2;" : "=f"(lo), "=f"(hi) : "l"(p));
}

// ---------------- input rearrange + pad (fp32) ----------------
__global__ void rearrange_pad_kernel(const float* __restrict__ sup, const float* __restrict__ qry,
                                     float* __restrict__ out)
{
    const int plane = blockIdx.y;
    const int clip = plane / 3;
    const int c = plane - clip * 3;
    const int s = blockIdx.x * blockDim.x + threadIdx.x;
    const int HWp = 114 * 114;
    if (s >= 18 * HWp) return;
    int dz = s / HWp;
    int r = s - dz * HWp;
    int hy = r / 114;
    int wx = r - hy * 114;
    float val = 0.0f;
    if (dz >= 1 && dz <= 16 && hy >= 1 && hy <= 112 && wx >= 1 && wx <= 112) {
        int tt = dz - 1, h = hy - 1, w = wx - 1;
        const float* src = (clip < 12) ? sup : qry;
        int cc = (clip < 12) ? clip : clip - 12;
        long addr = ((((long)cc * 16 + tt) * 3 + c) * 112 + h) * 112 + w;
        val = src[addr];
    }
    out[(long)plane * 18 * HWp + s] = val;
}

__global__ void w1prep_kernel(const float* __restrict__ w, float* __restrict__ out)
{
    int idx = blockIdx.x * blockDim.x + threadIdx.x;
    if (idx >= 64 * 96) return;
    int m = idx / 96, k = idx - m * 96;
    out[idx] = (k < 81) ? w[m * 81 + k] : 0.0f;
}

__global__ void wpack_kernel(const float* __restrict__ w, unsigned* __restrict__ out, int n)
{
    int i = blockIdx.x * blockDim.x + threadIdx.x;
    if (i < n) out[i] = pack_split(w[i]);
}

// ---------------- conv1: SIMT implicit GEMM (fp32, f32x2 FMA) ----------------
__global__ __launch_bounds__(256, 2)
void conv_gemm(const float* __restrict__ A, const float* __restrict__ inp,
               float* __restrict__ out, const float* __restrict__ bias, float scale,
               int Cin, int D, int H, int W, int Ktrue, int Kpad, int Cout, int Ntotal)
{
    constexpr int BM = 64, BNt = 128, BK = 16, MR = 4;
    const int Hp = H + 2, Wp = W + 2;
    const int HWp = Hp * Wp;
    const int chanStride = (D + 2) * HWp;
    const int HW = H * W;
    const int DHW = D * HW;

    __shared__ float sA[2][BK][BM];
    __shared__ float sB[2][BK][BNt];

    const int tid = threadIdx.x;
    const int tx = tid & 15;
    const int ty = tid >> 4;
    const int ntile = blockIdx.x;
    const int mtile = blockIdx.y;

    const int krow = ty;
    const int n0 = tx * 8;
    int nbase[8];
#pragma unroll
    for (int j = 0; j < 8; ++j) {
        int n = ntile * BNt + n0 + j;
        if (n >= Ntotal) n = Ntotal - 1;
        int b = n / DHW;
        int rem = n - b * DHW;
        int d = rem / HW;
        int r2 = rem - d * HW;
        int h = r2 / W;
        int w = r2 - h * W;
        nbase[j] = b * Cin * chanStride + d * HWp + h * Wp + w;
    }

    const int am = tid & (BM - 1);
    const int akg = tid / BM;
    const float* Aptr = A + (size_t)(mtile * BM + am) * Kpad;

    float4 stA0;
    float stB[8];
    int koff = 0;

    auto LOADK = [&](int k0_) {
        stA0 = *(const float4*)(Aptr + k0_ + akg * 4);
        int kg_ = k0_ + krow;
        int ke_ = (kg_ < Ktrue) ? kg_ : 0;
        int ci_ = ke_ / 27;
        int r_ = ke_ - ci_ * 27;
        int kd_ = r_ / 9; r_ -= kd_ * 9;
        int kh_ = r_ / 3;
        int kw_ = r_ - kh_ * 3;
        koff = ci_ * chanStride + kd_ * HWp + kh_ * Wp + kw_;
#pragma unroll
        for (int j = 0; j < 8; ++j) stB[j] = __ldg(inp + nbase[j] + koff);
    };
    auto STORETILE = [&](int bf_) {
        int kb_ = akg * 4;
        sA[bf_][kb_ + 0][am] = stA0.x;
        sA[bf_][kb_ + 1][am] = stA0.y;
        sA[bf_][kb_ + 2][am] = stA0.z;
        sA[bf_][kb_ + 3][am] = stA0.w;
        *(float4*)&sB[bf_][krow][n0]     = make_float4(stB[0], stB[1], stB[2], stB[3]);
        *(float4*)&sB[bf_][krow][n0 + 4] = make_float4(stB[4], stB[5], stB[6], stB[7]);
    };

    unsigned long long acc2[MR][4];
#pragma unroll
    for (int i = 0; i < MR; ++i)
#pragma unroll
        for (int jp = 0; jp < 4; ++jp) acc2[i][jp] = 0ULL;

    const int KT = Kpad / BK;
    LOADK(0);
    STORETILE(0);
    __syncthreads();

    for (int kt = 0; kt < KT; ++kt) {
        int buf = kt & 1;
        if (kt + 1 < KT) LOADK((kt + 1) * BK);
#pragma unroll
        for (int kk = 0; kk < BK; ++kk) {
            ulonglong2 b0 = *(const ulonglong2*)&sB[buf][kk][tx * 4];
            ulonglong2 b1 = *(const ulonglong2*)&sB[buf][kk][64 + tx * 4];
            unsigned long long bp[4] = {b0.x, b0.y, b1.x, b1.y};
            float4 a0 = *(const float4*)&sA[buf][kk][ty * 4];
            float af[MR] = {a0.x, a0.y, a0.z, a0.w};
#pragma unroll
            for (int i = 0; i < MR; ++i) {
                unsigned long long a2 = splat2(af[i]);
                ffma2(acc2[i][0], a2, bp[0]);
                ffma2(acc2[i][1], a2, bp[1]);
                ffma2(acc2[i][2], a2, bp[2]);
                ffma2(acc2[i][3], a2, bp[3]);
            }
        }
        if (kt + 1 < KT) STORETILE(buf ^ 1);
        __syncthreads();
    }

#pragma unroll
    for (int jp = 0; jp < 4; ++jp) {
        int colbase = (jp < 2) ? (tx * 4 + jp * 2) : (64 + tx * 4 + (jp - 2) * 2);
#pragma unroll
        for (int half = 0; half < 2; ++half) {
            int n = ntile * BNt + colbase + half;
            if (n >= Ntotal) continue;
            int b = n / DHW;
            int rem = n - b * DHW;
            size_t obase = ((size_t)b * Cout) * DHW + rem;
#pragma unroll
            for (int i = 0; i < MR; ++i) {
                int m = mtile * BM + ty * 4 + i;
                float lo, hi;
                unpack2(acc2[i][jp], lo, hi);
                float v = scale * (((half == 0) ? lo : hi) + bias[m]);
                out[obase + (size_t)m * DHW] = fmaxf(v, 0.0f);
            }
        }
    }
}

// ---------------- wmma split-bf16 conv (conv2..conv5b) ----------------
// GEMM: M=Cout (128/tile), N=spatial (128/tile), K chunks of 32.
// smem per buffer: A_hi/A_lo [128][40] bf16, B_hi/B_lo [128][40] bf16.
#define TCA_HI 0
#define TCA_LO 10240
#define TCB_HI 20480
#define TCB_LO 30720
#define TCBUF  40960

__global__ __launch_bounds__(256, 2)
void conv_tc(const unsigned* __restrict__ wpk, const unsigned* __restrict__ inp,
             float* __restrict__ out, const float* __restrict__ bias, float scale,
             int Cin, int D, int H, int W, int K, int Cout, int Ntotal)
{
    extern __shared__ char dsm[];
    char* albase = (char*)(((uintptr_t)dsm + 1023) & ~(uintptr_t)1023);

    const int Hp = H + 2, Wp = W + 2;
    const int HWp = Hp * Wp;
    const int chanStride = (D + 2) * HWp;
    const int HW = H * W;
    const int DHW = D * HW;

    const int t = threadIdx.x;
    const int wid = t >> 5;
    const int ntile = blockIdx.x;
    const int mtile = blockIdx.y;

    // ---- A gather mapping (coalesced along K): p = kpair, rbase = row ----
    const int p = t & 15;
    const int rbase = t >> 4;
    const unsigned* Awp = wpk + (size_t)(mtile * 128 + rbase) * K + 2 * p;

    // ---- B gather mapping (coalesced along N): nl = lane->n, kb = warp->4 k ----
    const int nl = t & 31;
    const int kb = (t >> 5) << 2;   // 0,4,...,28
    int nbB[4];
#pragma unroll
    for (int i = 0; i < 4; ++i) {
        int n = ntile * 128 + i * 32 + nl;
        if (n >= Ntotal) n = Ntotal - 1;
        int b = n / DHW;
        int rem = n - b * DHW;
        int d = rem / HW;
        int r2 = rem - d * HW;
        int h = r2 / W;
        int w = r2 - h * W;
        nbB[i] = b * Cin * chanStride + d * HWp + h * Wp + w;
    }

    uint2 aw[8];
    uint32_t bw[4][4];

    auto LOADC = [&](int k0) {
#pragma unroll
        for (int i = 0; i < 8; ++i)
            aw[i] = *(const uint2*)(Awp + (size_t)(16 * i) * K + k0);
        int ko[4];
#pragma unroll
        for (int j = 0; j < 4; ++j) {
            int k = k0 + kb + j;
            int ci = k / 27, r_ = k - ci * 27;
            int kd = r_ / 9; r_ -= kd * 9;
            int kh = r_ / 3, kw = r_ - kh * 3;
            ko[j] = ci * chanStride + kd * HWp + kh * Wp + kw;
        }
#pragma unroll
        for (int i = 0; i < 4; ++i)
#pragma unroll
            for (int j = 0; j < 4; ++j)
                bw[i][j] = __ldg(inp + nbB[i] + ko[j]);
    };

    auto STOREC = [&](char* sb) {
#pragma unroll
        for (int i = 0; i < 8; ++i) {
            int off = (rbase + 16 * i) * 80 + p * 4;
            uint32_t ahi, alo;
            asm("prmt.b32 %0, %1, %2, 0x5410;" : "=r"(ahi) : "r"(aw[i].x), "r"(aw[i].y));
            asm("prmt.b32 %0, %1, %2, 0x7632;" : "=r"(alo) : "r"(aw[i].x), "r"(aw[i].y));
            *(uint32_t*)(sb + TCA_HI + off) = ahi;
            *(uint32_t*)(sb + TCA_LO + off) = alo;
        }
#pragma unroll
        for (int i = 0; i < 4; ++i)
#pragma unroll
            for (int jp = 0; jp < 2; ++jp) {
                int j = jp * 2;
                uint32_t bhi, blo;
                asm("prmt.b32 %0, %1, %2, 0x5410;" : "=r"(bhi) : "r"(bw[i][j]), "r"(bw[i][j + 1]));
                asm("prmt.b32 %0, %1, %2, 0x7632;" : "=r"(blo) : "r"(bw[i][j]), "r"(bw[i][j + 1]));
                int off = (i * 32 + nl) * 80 + (kb + j) * 2;
                *(uint32_t*)(sb + TCB_HI + off) = bhi;
                *(uint32_t*)(sb + TCB_LO + off) = blo;
            }
    };

    // ---- accumulators: warp (wm, wn) owns 64x32 ----
    const int wm = wid >> 2;   // 0..1
    const int wn = wid & 3;    // 0..3
    wmma::fragment<wmma::accumulator, 16, 16, 16, float> acc[4][2];
#pragma unroll
    for (int i = 0; i < 4; ++i)
#pragma unroll
        for (int j = 0; j < 2; ++j) wmma::fill_fragment(acc[i][j], 0.0f);

    // register-lean compute: preload B frags (4), stream A frags just-in-time
    auto COMPUTE = [&](char* sb) {
        const __nv_bfloat16* Ahi = (const __nv_bfloat16*)(sb + TCA_HI);
        const __nv_bfloat16* Alo = (const __nv_bfloat16*)(sb + TCA_LO);
        const __nv_bfloat16* Bhi = (const __nv_bfloat16*)(sb + TCB_HI);
        const __nv_bfloat16* Blo = (const __nv_bfloat16*)(sb + TCB_LO);
#pragma unroll
        for (int ks = 0; ks < 2; ++ks) {
            wmma::fragment<wmma::matrix_b, 16, 16, 16, __nv_bfloat16, wmma::col_major> bh[2], bl[2];
#pragma unroll
            for (int j = 0; j < 2; ++j) {
                const int co = (wn * 32 + j * 16) * 40 + ks * 16;
                wmma::load_matrix_sync(bh[j], Bhi + co, 40);
                wmma::load_matrix_sync(bl[j], Blo + co, 40);
            }
#pragma unroll
            for (int i = 0; i < 4; ++i) {
                const int ro = (wm * 64 + i * 16) * 40 + ks * 16;
                wmma::fragment<wmma::matrix_a, 16, 16, 16, __nv_bfloat16, wmma::row_major> ah, al;
                wmma::load_matrix_sync(ah, Ahi + ro, 40);
                wmma::load_matrix_sync(al, Alo + ro, 40);
#pragma unroll
                for (int j = 0; j < 2; ++j) {
                    wmma::mma_sync(acc[i][j], ah, bh[j], acc[i][j]);
                    wmma::mma_sync(acc[i][j], ah, bl[j], acc[i][j]);
                    wmma::mma_sync(acc[i][j], al, bh[j], acc[i][j]);
                }
            }
        }
    };

    const int KT = K / 32;
    LOADC(0);
    STOREC(albase);
    __syncthreads();
    for (int kc = 0; kc < KT; ++kc) {
        char* cur = albase + (kc & 1) * TCBUF;
        char* nxt = albase + ((kc & 1) ^ 1) * TCBUF;
        if (kc + 1 < KT) LOADC((kc + 1) * 32);
        COMPUTE(cur);
        if (kc + 1 < KT) STOREC(nxt);
        __syncthreads();
    }

    // ---- epilogue: stage 128x128 fp32 in smem, coalesced scatter ----
    float* stage = (float*)albase;
#pragma unroll
    for (int i = 0; i < 4; ++i)
#pragma unroll
        for (int j = 0; j < 2; ++j)
            wmma::store_matrix_sync(stage + (wm * 64 + i * 16) * 132 + (wn * 32 + j * 16),
                                    acc[i][j], 132, wmma::mem_row_major);
    __syncthreads();
    {
        const int jn = t & 127, rh = t >> 7;
        const int n = ntile * 128 + jn;
        if (n < Ntotal) {
            int b = n / DHW, rem = n - b * DHW;
            size_t obase = ((size_t)b * Cout) * DHW + rem;
#pragma unroll 4
            for (int i = 0; i < 64; ++i) {
                int m = rh * 64 + i;
                int mg = mtile * 128 + m;
                float v = scale * (stage[m * 132 + jn] + bias[mg]);
                out[obase + (size_t)mg * DHW] = fmaxf(v, 0.0f);
            }
        }
    }
}

// ---------------- maxpool + pad (optionally writing packed split words) ----------------
__global__ void pool_pad_kernel(const float* __restrict__ in, float* __restrict__ out,
                                int D, int H, int W,
                                int kd, int kh, int kw, int sd, int sh, int sw,
                                int pd, int ph, int pw,
                                int Do, int Ho, int Wo, int cp, int split)
{
    const int plane = blockIdx.y;
    const int Hp = Ho + 2 * cp, Wp = Wo + 2 * cp, Dp = Do + 2 * cp;
    const int HWp = Hp * Wp;
    const int s = blockIdx.x * blockDim.x + threadIdx.x;
    if (s >= Dp * HWp) return;
    int z = s / HWp;
    int r = s - z * HWp;
    int y = r / Wp;
    int x = r - y * Wp;
    float v = 0.0f;
    int od = z - cp, oh = y - cp, ow = x - cp;
    if (od >= 0 && od < Do && oh >= 0 && oh < Ho && ow >= 0 && ow < Wo) {
        float m = -3.4e38f;
        int id0 = od * sd - pd, ih0 = oh * sh - ph, iw0 = ow * sw - pw;
        const float* base = in + (long)plane * D * H * W;
        for (int a = 0; a < kd; ++a) {
            int id = id0 + a;
            if (id < 0 || id >= D) continue;
            for (int e = 0; e < kh; ++e) {
                int ih = ih0 + e;
                if (ih < 0 || ih >= H) continue;
                for (int f = 0; f < kw; ++f) {
                    int iw = iw0 + f;
                    if (iw < 0 || iw >= W) continue;
                    float q = base[(id * H + ih) * W + iw];
                    m = fmaxf(m, q);
                }
            }
        }
        v = m;
    }
    if (split) ((unsigned*)out)[(long)plane * Dp * HWp + s] = pack_split(v);
    else out[(long)plane * Dp * HWp + s] = v;
}

// ---------------- tiled FC: warp-per-row, x chunk in smem ----------------
__global__ __launch_bounds__(256)
void fc_tile_kernel(const float* __restrict__ x, const float* __restrict__ W,
                    const float* __restrict__ b, float* __restrict__ y,
                    int K, int M, float scale)
{
    __shared__ float xs[24][260];
    const int warp = threadIdx.x >> 5, lane = threadIdx.x & 31;
    const int m = blockIdx.x * 8 + warp;
    float acc[24];
#pragma unroll
    for (int n = 0; n < 24; ++n) acc[n] = 0.0f;

    const float* wr = W + (size_t)m * K;
    for (int k0 = 0; k0 < K; k0 += 256) {
        __syncthreads();
        for (int i = threadIdx.x; i < 24 * 64; i += 256) {
            int n = i / 64, kq = i - n * 64;
            *(float4*)&xs[n][kq * 4] = *(const float4*)(x + (size_t)n * K + k0 + kq * 4);
        }
        __syncthreads();
#pragma unroll 2
        for (int kq = lane; kq < 64; kq += 32) {
            float4 w4 = *(const float4*)(wr + k0 + kq * 4);
#pragma unroll
            for (int n = 0; n < 24; ++n) {
                float4 x4 = *(const float4*)&xs[n][kq * 4];
                acc[n] += w4.x * x4.x + w4.y * x4.y + w4.z * x4.z + w4.w * x4.w;
            }
        }
    }
#pragma unroll
    for (int n = 0; n < 24; ++n) {
#pragma unroll
        for (int o = 16; o > 0; o >>= 1)
            acc[n] += __shfl_xor_sync(0xFFFFFFFFu, acc[n], o);
    }
    if (lane == 0) {
#pragma unroll
        for (int n = 0; n < 24; ++n) {
            float v = scale * (acc[n] + b[m]);
            y[(size_t)n * M + m] = fmaxf(v, 0.0f);
        }
    }
}

__global__ void rownorm_kernel(const float* __restrict__ x, float* __restrict__ nrm, int K)
{
    int row = blockIdx.x;
    float s = 0.0f;
    for (int k = threadIdx.x; k < K; k += 128) {
        float v = x[(size_t)row * K + k];
        s += v * v;
    }
    __shared__ float sm[128];
    sm[threadIdx.x] = s;
    __syncthreads();
    for (int o = 64; o > 0; o >>= 1) {
        if (threadIdx.x < o) sm[threadIdx.x] += sm[threadIdx.x + o];
        __syncthreads();
    }
    if (threadIdx.x == 0) nrm[row] = sqrtf(sm[0]);
}

__global__ void cost_kernel(const float* __restrict__ feat, const float* __restrict__ nrm,
                            float* __restrict__ cost)
{
    int bi = blockIdx.x;
    int j = bi & 3, t2 = bi >> 2;
    int i = t2 & 3, t3 = t2 >> 2;
    int s = t3 % 3, q = t3 / 3;
    int qrow = 12 + q * 4 + i;
    int srow = s * 4 + j;
    const float* a = feat + (size_t)qrow * 4096;
    const float* c = feat + (size_t)srow * 4096;
    float pr = 0.0f;
    for (int k = threadIdx.x; k < 4096; k += 128) pr += a[k] * c[k];
    __shared__ float sm[128];
    sm[threadIdx.x] = pr;
    __syncthreads();
    for (int o = 64; o > 0; o >>= 1) {
        if (threadIdx.x < o) sm[threadIdx.x] += sm[threadIdx.x + o];
        __syncthreads();
    }
    if (threadIdx.x == 0)
        cost[bi] = 1.0f - sm[0] / ((nrm[qrow] + 1e-8f) * (nrm[srow] + 1e-8f));
}

__global__ void sinkhorn_kernel(const float* __restrict__ cost, float* __restrict__ outp)
{
    int t = threadIdx.x;
    if (t >= 9) return;
    float sem[16], Km[16];
    for (int i = 0; i < 4; ++i)
        for (int j = 0; j < 4; ++j) {
            float sc = cost[t * 16 + i * 4 + j];
            float ti = i * 0.25f, tj = j * 0.25f;
            float d2 = (ti - tj) * (ti - tj);
            float pos = expf(-1.0f / (d2 + 1.0f));
            sem[i * 4 + j] = sc;
            Km[i * 4 + j] = expf(-7.0f * (sc + 0.4f * pos));
        }
    float u[4] = {0.25f, 0.25f, 0.25f, 0.25f}, v[4];
    for (int it = 0; it < 100; ++it) {
        for (int j = 0; j < 4; ++j) {
            float s = 1e-9f;
            for (int i = 0; i < 4; ++i) s += Km[i * 4 + j] * u[i];
            v[j] = 0.25f / s;
        }
        for (int i = 0; i < 4; ++i) {
            float s = 1e-9f;
            for (int j = 0; j < 4; ++j) s += Km[i * 4 + j] * v[j];
            u[i] = 0.25f / s;
        }
    }
    for (int j = 0; j < 4; ++j) {
        float s = 1e-9f;
        for (int i = 0; i < 4; ++i) s += Km[i * 4 + j] * u[i];
        v[j] = 0.25f / s;
    }
    float tr = 0.0f;
    for (int i = 0; i < 4; ++i)
        for (int j = 0; j < 4; ++j)
            tr += u[i] * Km[i * 4 + j] * v[j] * sem[i * 4 + j];
    outp[t] = -tr;
}

// ---------------- driver ----------------
static inline int cdiv_i(long a, long b) { return (int)((a + b - 1) / b); }

extern "C" void kernel_launch(void* const* d_in, const int* in_sizes, int n_in,
                              void* d_out, int out_size)
{
    const float* sup  = (const float*)d_in[0];
    const float* qry  = (const float*)d_in[1];
    const float* w1   = (const float*)d_in[2];
    const float* b1   = (const float*)d_in[3];
    const float* w2   = (const float*)d_in[4];
    const float* b2   = (const float*)d_in[5];
    const float* w3a  = (const float*)d_in[6];
    const float* b3a  = (const float*)d_in[7];
    const float* w3b  = (const float*)d_in[8];
    const float* b3b  = (const float*)d_in[9];
    const float* w4a  = (const float*)d_in[10];
    const float* b4a  = (const float*)d_in[11];
    const float* w4b  = (const float*)d_in[12];
    const float* b4b  = (const float*)d_in[13];
    const float* w5a  = (const float*)d_in[14];
    const float* b5a  = (const float*)d_in[15];
    const float* w5b  = (const float*)d_in[16];
    const float* b5b  = (const float*)d_in[17];
    const float* fw6  = (const float*)d_in[18];
    const float* fb6  = (const float*)d_in[19];
    const float* fw7  = (const float*)d_in[20];
    const float* fb7  = (const float*)d_in[21];

    float *pad, *act, *feat, *fc6o, *fc7o, *nrm, *cst, *w1p;
    unsigned* wpk;
    cudaGetSymbolAddress((void**)&pad,  g_pad);
    cudaGetSymbolAddress((void**)&act,  g_act);
    cudaGetSymbolAddress((void**)&feat, g_feat);
    cudaGetSymbolAddress((void**)&fc6o, g_fc6);
    cudaGetSymbolAddress((void**)&fc7o, g_fc7);
    cudaGetSymbolAddress((void**)&nrm,  g_norm);
    cudaGetSymbolAddress((void**)&cst,  g_cost);
    cudaGetSymbolAddress((void**)&w1p,  g_w1);
    cudaGetSymbolAddress((void**)&wpk,  g_wpk);

    const float SC = BN_SCALE_F;
    const int TC_SMEM = 2 * TCBUF + 1024;  // 83 KB
    cudaFuncSetAttribute(conv_tc, cudaFuncAttributeMaxDynamicSharedMemorySize, TC_SMEM);

    // weight packing offsets (words)
    const long O2 = 0, O3A = 221184, O3B = 1105920, O4A = 2875392;
    const long O4B = 6414336, O5A = 13492224, O5B = 20570112;

    rearrange_pad_kernel<<<dim3(cdiv_i(18 * 114 * 114, 256), 72), 256>>>(sup, qry, pad);
    w1prep_kernel<<<cdiv_i(64 * 96, 256), 256>>>(w1, w1p);
    wpack_kernel<<<cdiv_i(221184, 256), 256>>>(w2,  wpk + O2,  221184);
    wpack_kernel<<<cdiv_i(884736, 256), 256>>>(w3a, wpk + O3A, 884736);
    wpack_kernel<<<cdiv_i(1769472, 256), 256>>>(w3b, wpk + O3B, 1769472);
    wpack_kernel<<<cdiv_i(3538944, 256), 256>>>(w4a, wpk + O4A, 3538944);
    wpack_kernel<<<cdiv_i(7077888, 256), 256>>>(w4b, wpk + O4B, 7077888);
    wpack_kernel<<<cdiv_i(7077888, 256), 256>>>(w5a, wpk + O5A, 7077888);
    wpack_kernel<<<cdiv_i(7077888, 256), 256>>>(w5b, wpk + O5B, 7077888);

    // conv1 (SIMT fp32)
    conv_gemm<<<dim3(37632, 1), 256>>>(w1p, pad, act, b1, SC,
                                       3, 16, 112, 112, 81, 96, 64, 4816896);
    // pool1 + pad + split
    pool_pad_kernel<<<dim3(cdiv_i(18 * 58 * 58, 256), 24 * 64), 256>>>(
        act, pad, 16, 112, 112, 1, 2, 2, 1, 2, 2, 0, 0, 0, 16, 56, 56, 1, 1);
    // conv2
    conv_tc<<<dim3(9408, 1), 256, TC_SMEM>>>((unsigned*)(wpk + O2), (unsigned*)pad, act, b2, SC,
                                             64, 16, 56, 56, 1728, 128, 1204224);
    pool_pad_kernel<<<dim3(cdiv_i(10 * 30 * 30, 256), 24 * 128), 256>>>(
        act, pad, 16, 56, 56, 2, 2, 2, 2, 2, 2, 0, 0, 0, 8, 28, 28, 1, 1);
    // conv3a
    conv_tc<<<dim3(1176, 2), 256, TC_SMEM>>>((unsigned*)(wpk + O3A), (unsigned*)pad, act, b3a, 1.0f,
                                             128, 8, 28, 28, 3456, 256, 150528);
    pool_pad_kernel<<<dim3(cdiv_i(10 * 30 * 30, 256), 24 * 256), 256>>>(
        act, pad, 8, 28, 28, 1, 1, 1, 1, 1, 1, 0, 0, 0, 8, 28, 28, 1, 1);
    // conv3b
    conv_tc<<<dim3(1176, 2), 256, TC_SMEM>>>((unsigned*)(wpk + O3B), (unsigned*)pad, act, b3b, SC,
                                             256, 8, 28, 28, 6912, 256, 150528);
    pool_pad_kernel<<<dim3(cdiv_i(6 * 16 * 16, 256), 24 * 256), 256>>>(
        act, pad, 8, 28, 28, 2, 2, 2, 2, 2, 2, 0, 0, 0, 4, 14, 14, 1, 1);
    // conv4a
    conv_tc<<<dim3(147, 4), 256, TC_SMEM>>>((unsigned*)(wpk + O4A), (unsigned*)pad, act, b4a, 1.0f,
                                            256, 4, 14, 14, 6912, 512, 18816);
    pool_pad_kernel<<<dim3(cdiv_i(6 * 16 * 16, 256), 24 * 512), 256>>>(
        act, pad, 4, 14, 14, 1, 1, 1, 1, 1, 1, 0, 0, 0, 4, 14, 14, 1, 1);
    // conv4b
    conv_tc<<<dim3(147, 4), 256, TC_SMEM>>>((unsigned*)(wpk + O4B), (unsigned*)pad, act, b4b, SC,
                                            512, 4, 14, 14, 13824, 512, 18816);
    pool_pad_kernel<<<dim3(cdiv_i(4 * 9 * 9, 256), 24 * 512), 256>>>(
        act, pad, 4, 14, 14, 2, 2, 2, 2, 2, 2, 0, 0, 0, 2, 7, 7, 1, 1);
    // conv5a
    conv_tc<<<dim3(19, 4), 256, TC_SMEM>>>((unsigned*)(wpk + O5A), (unsigned*)pad, act, b5a, 1.0f,
                                           512, 2, 7, 7, 13824, 512, 2352);
    pool_pad_kernel<<<dim3(cdiv_i(4 * 9 * 9, 256), 24 * 512), 256>>>(
        act, pad, 2, 7, 7, 1, 1, 1, 1, 1, 1, 0, 0, 0, 2, 7, 7, 1, 1);
    // conv5b
    conv_tc<<<dim3(19, 4), 256, TC_SMEM>>>((unsigned*)(wpk + O5B), (unsigned*)pad, act, b5b, SC,
                                           512, 2, 7, 7, 13824, 512, 2352);
    // pool5 -> features (fp32)
    pool_pad_kernel<<<dim3(1, 24 * 512), 256>>>(
        act, feat, 2, 7, 7, 2, 2, 2, 2, 2, 2, 0, 1, 1, 1, 4, 4, 0, 0);
    // fc6, fc7 (tiled)
    fc_tile_kernel<<<512, 256>>>(feat, fw6, fb6, fc6o, 8192, 4096, SC);
    fc_tile_kernel<<<512, 256>>>(fc6o, fw7, fb7, fc7o, 4096, 4096, SC);
    // head
    rownorm_kernel<<<24, 128>>>(fc7o, nrm, 4096);
    cost_kernel<<<144, 128>>>(fc7o, nrm, cst);
    sinkhorn_kernel<<<1, 32>>>(cst, (float*)d_out);
}

// round 12
// speedup vs baseline: 2.2185x; 1.1163x over previous
#include <cuda_runtime.h>
#include <cuda_bf16.h>
#include <mma.h>
#include <math.h>
#include <stdint.h>

using namespace nvcuda;

#define BN_SCALE_F 0.9999950000374996f

// ---------------- static scratch ----------------
__device__ float g_pad[93007872];
__device__ float g_act[308281344];
__device__ float g_feat[24 * 8192];
__device__ float g_fc6[24 * 4096];
__device__ float g_fc7[24 * 4096];
__device__ float g_norm[24];
__device__ float g_cost[144];
__device__ unsigned short g_wh[27654144];  // bf16 hi planes: conv2..conv5b, then conv1(Kpad 96)
__device__ unsigned short g_wl[27654144];  // bf16 lo planes

// ---------------- helpers ----------------
__device__ __forceinline__ unsigned pack_split(float v) {
    float hf = __uint_as_float(__float_as_uint(v) & 0xFFFF0000u);  // truncate-to-bf16 hi
    unsigned hi = __float_as_uint(hf) >> 16;
    float r = v - hf;
    unsigned lo = __float_as_uint(r) >> 16;                        // truncated lo
    return hi | (lo << 16);
}
__device__ __forceinline__ uint32_t smem_u32(const void* p) {
    uint32_t a;
    asm("{ .reg .u64 t; cvta.to.shared.u64 t, %1; cvt.u32.u64 %0, t; }" : "=r"(a) : "l"(p));
    return a;
}
__device__ __forceinline__ void cp_async8(uint32_t dst, const void* src) {
    asm volatile("cp.async.ca.shared.global [%0], [%1], 8;" :: "r"(dst), "l"(src));
}

// ---------------- input rearrange + pad -> packed split words ----------------
__global__ void rearrange_pad_kernel(const float* __restrict__ sup, const float* __restrict__ qry,
                                     unsigned* __restrict__ out)
{
    const int plane = blockIdx.y;
    const int clip = plane / 3;
    const int c = plane - clip * 3;
    const int s = blockIdx.x * blockDim.x + threadIdx.x;
    const int HWp = 114 * 114;
    if (s >= 18 * HWp) return;
    int dz = s / HWp;
    int r = s - dz * HWp;
    int hy = r / 114;
    int wx = r - hy * 114;
    float val = 0.0f;
    if (dz >= 1 && dz <= 16 && hy >= 1 && hy <= 112 && wx >= 1 && wx <= 112) {
        int tt = dz - 1, h = hy - 1, w = wx - 1;
        const float* src = (clip < 12) ? sup : qry;
        int cc = (clip < 12) ? clip : clip - 12;
        long addr = ((((long)cc * 16 + tt) * 3 + c) * 112 + h) * 112 + w;
        val = src[addr];
    }
    out[(long)plane * 18 * HWp + s] = pack_split(val);
}

// split weights fp32 -> separate bf16 hi/lo planes, optional K padding
__global__ void wsplit_kernel(const float* __restrict__ w, unsigned short* __restrict__ hi,
                              unsigned short* __restrict__ lo, int Ktrue, int Kpad, int total)
{
    int idx = blockIdx.x * blockDim.x + threadIdx.x;
    if (idx >= total) return;
    int m = idx / Kpad, k = idx - m * Kpad;
    float v = (k < Ktrue) ? w[m * Ktrue + k] : 0.0f;
    float hf = __uint_as_float(__float_as_uint(v) & 0xFFFF0000u);
    hi[idx] = (unsigned short)(__float_as_uint(v) >> 16);
    lo[idx] = (unsigned short)(__float_as_uint(v - hf) >> 16);
}

// ---------------- wmma split-bf16 conv (all conv layers) ----------------
// GEMM: M=Cout (BM/tile), N=spatial (128/tile), K chunks of 32.
// A (weights): dense bf16 hi/lo planes -> cp.async to smem.
// B (acts): packed split words, register gather + prmt.
template<int BM>
__global__ __launch_bounds__(256, 2)
void conv_tc(const unsigned short* __restrict__ wh, const unsigned short* __restrict__ wl,
             const unsigned* __restrict__ inp, float* __restrict__ out,
             const float* __restrict__ bias, float scale,
             int Cin, int D, int H, int W, int Ktrue, int K, int Cout, int Ntotal)
{
    constexpr int ASZ  = BM * 80;         // bytes per A plane (stride 40 bf16)
    constexpr int BHI  = 2 * ASZ;
    constexpr int BLO  = BHI + 10240;
    constexpr int TCB  = BHI + 20480;     // bytes per buffer
    constexpr int AI   = BM / 32;         // A frags per warp half
    extern __shared__ char dsm[];
    char* albase = (char*)(((uintptr_t)dsm + 1023) & ~(uintptr_t)1023);
    const uint32_t sbase = smem_u32(albase);

    const int Hp = H + 2, Wp = W + 2;
    const int HWp = Hp * Wp;
    const int chanStride = (D + 2) * HWp;
    const int HW = H * W;
    const int DHW = D * HW;

    const int t = threadIdx.x;
    const int wid = t >> 5;
    const int ntile = blockIdx.x;
    const int mtile = blockIdx.y;

    // ---- A: cp.async dense copy (BM x 32 bf16 per plane per chunk) ----
    auto CPA = [&](int bufIdx, int k0) {
        uint32_t dst0 = sbase + bufIdx * TCB;
#pragma unroll
        for (int i = 0; i < BM / 16; ++i) {        // (BM*8*2)/256 chunks of 8B per thread
            int c = t + 256 * i;
            int plane = c / (BM * 8);
            int rem = c - plane * (BM * 8);
            int row = rem >> 3, q = rem & 7;
            const unsigned short* src = (plane ? wl : wh) + (size_t)(mtile * BM + row) * K + k0 + q * 4;
            cp_async8(dst0 + plane * ASZ + row * 80 + q * 8, src);
        }
        asm volatile("cp.async.commit_group;");
    };

    // ---- B gather (coalesced along N): nl = lane->n, kb = warp->4 k ----
    const int nl = t & 31;
    const int kb = (t >> 5) << 2;
    int nbB[4];
#pragma unroll
    for (int i = 0; i < 4; ++i) {
        int n = ntile * 128 + i * 32 + nl;
        if (n >= Ntotal) n = Ntotal - 1;
        int b = n / DHW;
        int rem = n - b * DHW;
        int d = rem / HW;
        int r2 = rem - d * HW;
        int h = r2 / W;
        int w = r2 - h * W;
        nbB[i] = b * Cin * chanStride + d * HWp + h * Wp + w;
    }

    uint32_t bw[4][4];
    auto LOADB = [&](int k0) {
        int ko[4];
#pragma unroll
        for (int j = 0; j < 4; ++j) {
            int k = k0 + kb + j;
            if (k >= Ktrue) k = 0;   // padded K: weight is 0, any valid addr
            int ci = k / 27, r_ = k - ci * 27;
            int kd = r_ / 9; r_ -= kd * 9;
            int kh = r_ / 3, kw = r_ - kh * 3;
            ko[j] = ci * chanStride + kd * HWp + kh * Wp + kw;
        }
#pragma unroll
        for (int i = 0; i < 4; ++i)
#pragma unroll
            for (int j = 0; j < 4; ++j)
                bw[i][j] = __ldg(inp + nbB[i] + ko[j]);
    };
    auto STOREB = [&](char* sb) {
#pragma unroll
        for (int i = 0; i < 4; ++i)
#pragma unroll
            for (int jp = 0; jp < 2; ++jp) {
                int j = jp * 2;
                uint32_t bhi, blo;
                asm("prmt.b32 %0, %1, %2, 0x5410;" : "=r"(bhi) : "r"(bw[i][j]), "r"(bw[i][j + 1]));
                asm("prmt.b32 %0, %1, %2, 0x7632;" : "=r"(blo) : "r"(bw[i][j]), "r"(bw[i][j + 1]));
                int off = (i * 32 + nl) * 80 + (kb + j) * 2;
                *(uint32_t*)(sb + BHI + off) = bhi;
                *(uint32_t*)(sb + BLO + off) = blo;
            }
    };

    // ---- accumulators: warp (wm, wn) owns (BM/2) x 32 ----
    const int wm = wid >> 2;
    const int wn = wid & 3;
    wmma::fragment<wmma::accumulator, 16, 16, 16, float> acc[AI][2];
#pragma unroll
    for (int i = 0; i < AI; ++i)
#pragma unroll
        for (int j = 0; j < 2; ++j) wmma::fill_fragment(acc[i][j], 0.0f);

    auto COMPUTE = [&](char* sb) {
        const __nv_bfloat16* Ahi = (const __nv_bfloat16*)(sb);
        const __nv_bfloat16* Alo = (const __nv_bfloat16*)(sb + ASZ);
        const __nv_bfloat16* Bhi = (const __nv_bfloat16*)(sb + BHI);
        const __nv_bfloat16* Blo = (const __nv_bfloat16*)(sb + BLO);
#pragma unroll
        for (int ks = 0; ks < 2; ++ks) {
            wmma::fragment<wmma::matrix_b, 16, 16, 16, __nv_bfloat16, wmma::col_major> bh[2], bl[2];
#pragma unroll
            for (int j = 0; j < 2; ++j) {
                const int co = (wn * 32 + j * 16) * 40 + ks * 16;
                wmma::load_matrix_sync(bh[j], Bhi + co, 40);
                wmma::load_matrix_sync(bl[j], Blo + co, 40);
            }
#pragma unroll
            for (int i = 0; i < AI; ++i) {
                const int ro = (wm * (BM / 2) + i * 16) * 40 + ks * 16;
                wmma::fragment<wmma::matrix_a, 16, 16, 16, __nv_bfloat16, wmma::row_major> ah, al;
                wmma::load_matrix_sync(ah, Ahi + ro, 40);
                wmma::load_matrix_sync(al, Alo + ro, 40);
#pragma unroll
                for (int j = 0; j < 2; ++j) {
                    wmma::mma_sync(acc[i][j], ah, bh[j], acc[i][j]);
                    wmma::mma_sync(acc[i][j], ah, bl[j], acc[i][j]);
                    wmma::mma_sync(acc[i][j], al, bh[j], acc[i][j]);
                }
            }
        }
    };

    const int KT = K / 32;
    CPA(0, 0);
    LOADB(0);
    asm volatile("cp.async.wait_group 0;" ::: "memory");
    STOREB(albase);
    __syncthreads();
    for (int kc = 0; kc < KT; ++kc) {
        char* cur = albase + (kc & 1) * TCB;
        char* nxt = albase + ((kc & 1) ^ 1) * TCB;
        if (kc + 1 < KT) {
            CPA((kc & 1) ^ 1, (kc + 1) * 32);
            LOADB((kc + 1) * 32);
        }
        COMPUTE(cur);
        if (kc + 1 < KT) {
            asm volatile("cp.async.wait_group 0;" ::: "memory");
            STOREB(nxt);
        }
        __syncthreads();
    }

    // ---- epilogue: stage BMx128 fp32 in smem, coalesced scatter ----
    float* stage = (float*)albase;
#pragma unroll
    for (int i = 0; i < AI; ++i)
#pragma unroll
        for (int j = 0; j < 2; ++j)
            wmma::store_matrix_sync(stage + (wm * (BM / 2) + i * 16) * 132 + (wn * 32 + j * 16),
                                    acc[i][j], 132, wmma::mem_row_major);
    __syncthreads();
    {
        const int jn = t & 127, rh = t >> 7;
        const int n = ntile * 128 + jn;
        if (n < Ntotal) {
            int b = n / DHW, rem = n - b * DHW;
            size_t obase = ((size_t)b * Cout) * DHW + rem;
#pragma unroll 4
            for (int i = 0; i < BM / 2; ++i) {
                int m = rh * (BM / 2) + i;
                int mg = mtile * BM + m;
                float v = scale * (stage[m * 132 + jn] + bias[mg]);
                out[obase + (size_t)mg * DHW] = fmaxf(v, 0.0f);
            }
        }
    }
}

// ---------------- maxpool + pad (optionally writing packed split words) ----------------
__global__ void pool_pad_kernel(const float* __restrict__ in, float* __restrict__ out,
                                int D, int H, int W,
                                int kd, int kh, int kw, int sd, int sh, int sw,
                                int pd, int ph, int pw,
                                int Do, int Ho, int Wo, int cp, int split)
{
    const int plane = blockIdx.y;
    const int Hp = Ho + 2 * cp, Wp = Wo + 2 * cp, Dp = Do + 2 * cp;
    const int HWp = Hp * Wp;
    const int s = blockIdx.x * blockDim.x + threadIdx.x;
    if (s >= Dp * HWp) return;
    int z = s / HWp;
    int r = s - z * HWp;
    int y = r / Wp;
    int x = r - y * Wp;
    float v = 0.0f;
    int od = z - cp, oh = y - cp, ow = x - cp;
    if (od >= 0 && od < Do && oh >= 0 && oh < Ho && ow >= 0 && ow < Wo) {
        float m = -3.4e38f;
        int id0 = od * sd - pd, ih0 = oh * sh - ph, iw0 = ow * sw - pw;
        const float* base = in + (long)plane * D * H * W;
        for (int a = 0; a < kd; ++a) {
            int id = id0 + a;
            if (id < 0 || id >= D) continue;
            for (int e = 0; e < kh; ++e) {
                int ih = ih0 + e;
                if (ih < 0 || ih >= H) continue;
                for (int f = 0; f < kw; ++f) {
                    int iw = iw0 + f;
                    if (iw < 0 || iw >= W) continue;
                    float q = base[(id * H + ih) * W + iw];
                    m = fmaxf(m, q);
                }
            }
        }
        v = m;
    }
    if (split) ((unsigned*)out)[(long)plane * Dp * HWp + s] = pack_split(v);
    else out[(long)plane * Dp * HWp + s] = v;
}

// ---------------- tiled FC: warp-per-row, x chunk in smem ----------------
__global__ __launch_bounds__(256)
void fc_tile_kernel(const float* __restrict__ x, const float* __restrict__ W,
                    const float* __restrict__ b, float* __restrict__ y,
                    int K, int M, float scale)
{
    __shared__ float xs[24][260];
    const int warp = threadIdx.x >> 5, lane = threadIdx.x & 31;
    const int m = blockIdx.x * 8 + warp;
    float acc[24];
#pragma unroll
    for (int n = 0; n < 24; ++n) acc[n] = 0.0f;

    const float* wr = W + (size_t)m * K;
    for (int k0 = 0; k0 < K; k0 += 256) {
        __syncthreads();
        for (int i = threadIdx.x; i < 24 * 64; i += 256) {
            int n = i / 64, kq = i - n * 64;
            *(float4*)&xs[n][kq * 4] = *(const float4*)(x + (size_t)n * K + k0 + kq * 4);
        }
        __syncthreads();
#pragma unroll 2
        for (int kq = lane; kq < 64; kq += 32) {
            float4 w4 = *(const float4*)(wr + k0 + kq * 4);
#pragma unroll
            for (int n = 0; n < 24; ++n) {
                float4 x4 = *(const float4*)&xs[n][kq * 4];
                acc[n] += w4.x * x4.x + w4.y * x4.y + w4.z * x4.z + w4.w * x4.w;
            }
        }
    }
#pragma unroll
    for (int n = 0; n < 24; ++n) {
#pragma unroll
        for (int o = 16; o > 0; o >>= 1)
            acc[n] += __shfl_xor_sync(0xFFFFFFFFu, acc[n], o);
    }
    if (lane == 0) {
#pragma unroll
        for (int n = 0; n < 24; ++n) {
            float v = scale * (acc[n] + b[m]);
            y[(size_t)n * M + m] = fmaxf(v, 0.0f);
        }
    }
}

__global__ void rownorm_kernel(const float* __restrict__ x, float* __restrict__ nrm, int K)
{
    int row = blockIdx.x;
    float s = 0.0f;
    for (int k = threadIdx.x; k < K; k += 128) {
        float v = x[(size_t)row * K + k];
        s += v * v;
    }
    __shared__ float sm[128];
    sm[threadIdx.x] = s;
    __syncthreads();
    for (int o = 64; o > 0; o >>= 1) {
        if (threadIdx.x < o) sm[threadIdx.x] += sm[threadIdx.x + o];
        __syncthreads();
    }
    if (threadIdx.x == 0) nrm[row] = sqrtf(sm[0]);
}

__global__ void cost_kernel(const float* __restrict__ feat, const float* __restrict__ nrm,
                            float* __restrict__ cost)
{
    int bi = blockIdx.x;
    int j = bi & 3, t2 = bi >> 2;
    int i = t2 & 3, t3 = t2 >> 2;
    int s = t3 % 3, q = t3 / 3;
    int qrow = 12 + q * 4 + i;
    int srow = s * 4 + j;
    const float* a = feat + (size_t)qrow * 4096;
    const float* c = feat + (size_t)srow * 4096;
    float pr = 0.0f;
    for (int k = threadIdx.x; k < 4096; k += 128) pr += a[k] * c[k];
    __shared__ float sm[128];
    sm[threadIdx.x] = pr;
    __syncthreads();
    for (int o = 64; o > 0; o >>= 1) {
        if (threadIdx.x < o) sm[threadIdx.x] += sm[threadIdx.x + o];
        __syncthreads();
    }
    if (threadIdx.x == 0)
        cost[bi] = 1.0f - sm[0] / ((nrm[qrow] + 1e-8f) * (nrm[srow] + 1e-8f));
}

__global__ void sinkhorn_kernel(const float* __restrict__ cost, float* __restrict__ outp)
{
    int t = threadIdx.x;
    if (t >= 9) return;
    float sem[16], Km[16];
    for (int i = 0; i < 4; ++i)
        for (int j = 0; j < 4; ++j) {
            float sc = cost[t * 16 + i * 4 + j];
            float ti = i * 0.25f, tj = j * 0.25f;
            float d2 = (ti - tj) * (ti - tj);
            float pos = expf(-1.0f / (d2 + 1.0f));
            sem[i * 4 + j] = sc;
            Km[i * 4 + j] = expf(-7.0f * (sc + 0.4f * pos));
        }
    float u[4] = {0.25f, 0.25f, 0.25f, 0.25f}, v[4];
    for (int it = 0; it < 100; ++it) {
        for (int j = 0; j < 4; ++j) {
            float s = 1e-9f;
            for (int i = 0; i < 4; ++i) s += Km[i * 4 + j] * u[i];
            v[j] = 0.25f / s;
        }
        for (int i = 0; i < 4; ++i) {
            float s = 1e-9f;
            for (int j = 0; j < 4; ++j) s += Km[i * 4 + j] * v[j];
            u[i] = 0.25f / s;
        }
    }
    for (int j = 0; j < 4; ++j) {
        float s = 1e-9f;
        for (int i = 0; i < 4; ++i) s += Km[i * 4 + j] * u[i];
        v[j] = 0.25f / s;
    }
    float tr = 0.0f;
    for (int i = 0; i < 4; ++i)
        for (int j = 0; j < 4; ++j)
            tr += u[i] * Km[i * 4 + j] * v[j] * sem[i * 4 + j];
    outp[t] = -tr;
}

// ---------------- driver ----------------
static inline int cdiv_i(long a, long b) { return (int)((a + b - 1) / b); }

extern "C" void kernel_launch(void* const* d_in, const int* in_sizes, int n_in,
                              void* d_out, int out_size)
{
    const float* sup  = (const float*)d_in[0];
    const float* qry  = (const float*)d_in[1];
    const float* w1   = (const float*)d_in[2];
    const float* b1   = (const float*)d_in[3];
    const float* w2   = (const float*)d_in[4];
    const float* b2   = (const float*)d_in[5];
    const float* w3a  = (const float*)d_in[6];
    const float* b3a  = (const float*)d_in[7];
    const float* w3b  = (const float*)d_in[8];
    const float* b3b  = (const float*)d_in[9];
    const float* w4a  = (const float*)d_in[10];
    const float* b4a  = (const float*)d_in[11];
    const float* w4b  = (const float*)d_in[12];
    const float* b4b  = (const float*)d_in[13];
    const float* w5a  = (const float*)d_in[14];
    const float* b5a  = (const float*)d_in[15];
    const float* w5b  = (const float*)d_in[16];
    const float* b5b  = (const float*)d_in[17];
    const float* fw6  = (const float*)d_in[18];
    const float* fb6  = (const float*)d_in[19];
    const float* fw7  = (const float*)d_in[20];
    const float* fb7  = (const float*)d_in[21];

    float *pad, *act, *feat, *fc6o, *fc7o, *nrm, *cst;
    unsigned short *wh, *wl;
    cudaGetSymbolAddress((void**)&pad,  g_pad);
    cudaGetSymbolAddress((void**)&act,  g_act);
    cudaGetSymbolAddress((void**)&feat, g_feat);
    cudaGetSymbolAddress((void**)&fc6o, g_fc6);
    cudaGetSymbolAddress((void**)&fc7o, g_fc7);
    cudaGetSymbolAddress((void**)&nrm,  g_norm);
    cudaGetSymbolAddress((void**)&cst,  g_cost);
    cudaGetSymbolAddress((void**)&wh,   g_wh);
    cudaGetSymbolAddress((void**)&wl,   g_wl);

    const float SC = BN_SCALE_F;
    const int TC_SMEM128 = 2 * (2 * 128 * 80 + 20480) + 1024;  // 82944
    const int TC_SMEM64  = 2 * (2 * 64 * 80 + 20480) + 1024;   // 62464
    cudaFuncSetAttribute(conv_tc<128>, cudaFuncAttributeMaxDynamicSharedMemorySize, TC_SMEM128);
    cudaFuncSetAttribute(conv_tc<64>,  cudaFuncAttributeMaxDynamicSharedMemorySize, TC_SMEM64);

    // weight plane offsets (elements)
    const long O2 = 0, O3A = 221184, O3B = 1105920, O4A = 2875392;
    const long O4B = 6414336, O5A = 13492224, O5B = 20570112, O1 = 27648000;

    rearrange_pad_kernel<<<dim3(cdiv_i(18 * 114 * 114, 256), 72), 256>>>(sup, qry, (unsigned*)pad);
    wsplit_kernel<<<cdiv_i(6144, 256), 256>>>(w1, wh + O1, wl + O1, 81, 96, 6144);
    wsplit_kernel<<<cdiv_i(221184, 256), 256>>>(w2,  wh + O2,  wl + O2,  1728, 1728, 221184);
    wsplit_kernel<<<cdiv_i(884736, 256), 256>>>(w3a, wh + O3A, wl + O3A, 3456, 3456, 884736);
    wsplit_kernel<<<cdiv_i(1769472, 256), 256>>>(w3b, wh + O3B, wl + O3B, 6912, 6912, 1769472);
    wsplit_kernel<<<cdiv_i(3538944, 256), 256>>>(w4a, wh + O4A, wl + O4A, 6912, 6912, 3538944);
    wsplit_kernel<<<cdiv_i(7077888, 256), 256>>>(w4b, wh + O4B, wl + O4B, 13824, 13824, 7077888);
    wsplit_kernel<<<cdiv_i(7077888, 256), 256>>>(w5a, wh + O5A, wl + O5A, 13824, 13824, 7077888);
    wsplit_kernel<<<cdiv_i(7077888, 256), 256>>>(w5b, wh + O5B, wl + O5B, 13824, 13824, 7077888);

    // conv1 (tensor path, BM=64, K 81->96)
    conv_tc<64><<<dim3(37632, 1), 256, TC_SMEM64>>>(wh + O1, wl + O1, (unsigned*)pad, act, b1, SC,
                                                    3, 16, 112, 112, 81, 96, 64, 4816896);
    // pool1 + pad + split
    pool_pad_kernel<<<dim3(cdiv_i(18 * 58 * 58, 256), 24 * 64), 256>>>(
        act, pad, 16, 112, 112, 1, 2, 2, 1, 2, 2, 0, 0, 0, 16, 56, 56, 1, 1);
    // conv2
    conv_tc<128><<<dim3(9408, 1), 256, TC_SMEM128>>>(wh + O2, wl + O2, (unsigned*)pad, act, b2, SC,
                                                     64, 16, 56, 56, 1728, 1728, 128, 1204224);
    pool_pad_kernel<<<dim3(cdiv_i(10 * 30 * 30, 256), 24 * 128), 256>>>(
        act, pad, 16, 56, 56, 2, 2, 2, 2, 2, 2, 0, 0, 0, 8, 28, 28, 1, 1);
    // conv3a
    conv_tc<128><<<dim3(1176, 2), 256, TC_SMEM128>>>(wh + O3A, wl + O3A, (unsigned*)pad, act, b3a, 1.0f,
                                                     128, 8, 28, 28, 3456, 3456, 256, 150528);
    pool_pad_kernel<<<dim3(cdiv_i(10 * 30 * 30, 256), 24 * 256), 256>>>(
        act, pad, 8, 28, 28, 1, 1, 1, 1, 1, 1, 0, 0, 0, 8, 28, 28, 1, 1);
    // conv3b
    conv_tc<128><<<dim3(1176, 2), 256, TC_SMEM128>>>(wh + O3B, wl + O3B, (unsigned*)pad, act, b3b, SC,
                                                     256, 8, 28, 28, 6912, 6912, 256, 150528);
    pool_pad_kernel<<<dim3(cdiv_i(6 * 16 * 16, 256), 24 * 256), 256>>>(
        act, pad, 8, 28, 28, 2, 2, 2, 2, 2, 2, 0, 0, 0, 4, 14, 14, 1, 1);
    // conv4a
    conv_tc<128><<<dim3(147, 4), 256, TC_SMEM128>>>(wh + O4A, wl + O4A, (unsigned*)pad, act, b4a, 1.0f,
                                                    256, 4, 14, 14, 6912, 6912, 512, 18816);
    pool_pad_kernel<<<dim3(cdiv_i(6 * 16 * 16, 256), 24 * 512), 256>>>(
        act, pad, 4, 14, 14, 1, 1, 1, 1, 1, 1, 0, 0, 0, 4, 14, 14, 1, 1);
    // conv4b
    conv_tc<128><<<dim3(147, 4), 256, TC_SMEM128>>>(wh + O4B, wl + O4B, (unsigned*)pad, act, b4b, SC,
                                                    512, 4, 14, 14, 13824, 13824, 512, 18816);
    pool_pad_kernel<<<dim3(cdiv_i(4 * 9 * 9, 256), 24 * 512), 256>>>(
        act, pad, 4, 14, 14, 2, 2, 2, 2, 2, 2, 0, 0, 0, 2, 7, 7, 1, 1);
    // conv5a
    conv_tc<128><<<dim3(19, 4), 256, TC_SMEM128>>>(wh + O5A, wl + O5A, (unsigned*)pad, act, b5a, 1.0f,
                                                   512, 2, 7, 7, 13824, 13824, 512, 2352);
    pool_pad_kernel<<<dim3(cdiv_i(4 * 9 * 9, 256), 24 * 512), 256>>>(
        act, pad, 2, 7, 7, 1, 1, 1, 1, 1, 1, 0, 0, 0, 2, 7, 7, 1, 1);
    // conv5b
    conv_tc<128><<<dim3(19, 4), 256, TC_SMEM128>>>(wh + O5B, wl + O5B, (unsigned*)pad, act, b5b, SC,
                                                   512, 2, 7, 7, 13824, 13824, 512, 2352);
    // pool5 -> features (fp32)
    pool_pad_kernel<<<dim3(1, 24 * 512), 256>>>(
        act, feat, 2, 7, 7, 2, 2, 2, 2, 2, 2, 0, 1, 1, 1, 4, 4, 0, 0);
    // fc6, fc7 (tiled)
    fc_tile_kernel<<<512, 256>>>(feat, fw6, fb6, fc6o, 8192, 4096, SC);
    fc_tile_kernel<<<512, 256>>>(fc6o, fw7, fb7, fc7o, 4096, 4096, SC);
    // head
    rownorm_kernel<<<24, 128>>>(fc7o, nrm, 4096);
    cost_kernel<<<144, 128>>>(fc7o, nrm, cst);
    sinkhorn_kernel<<<1, 32>>>(cst, (float*)d_out);
}